// round 9
// baseline (speedup 1.0000x reference)
#include <cuda_runtime.h>
#include <cuda_fp16.h>
#include <stdint.h>
#include <math.h>

// ---------------- problem constants ----------------
constexpr int BB   = 4;
constexpr int CC   = 512;
constexpr int TT   = 16;
constexpr int HWc  = 1024;
constexpr int NN   = BB * HWc;      // 4096
constexpr int MM   = NN * TT;       // 65536
constexpr int NH   = 8;
constexpr int CH   = 64;
constexpr int GRP  = 32;
constexpr int CPG  = CC / GRP;      // 16
constexpr int C3   = 3 * CC;        // 1536
constexpr float EPSF = 1e-6f;

// ---------------- scratch (static device globals) ----------------
__device__ float g_mean[BB * GRP * HWc];
__device__ float g_rstd[BB * GRP * HWc];
__device__ __half g_nh[(size_t)MM * CC];    // normed activations (fp16)
__device__ __half g_wqh[C3 * CC];           // qkv weights (fp16)
__device__ __half g_wph[CC * CC];           // proj weights (fp16)
__device__ __half g_qkv[(size_t)MM * C3];   // qkv output (fp16)
__device__ __half g_ah[(size_t)MM * CC];    // attention out (fp16)
__device__ float g_pout[(size_t)MM * CC];

// ---------------- helpers ----------------
__device__ __forceinline__ uint32_t smem_u32(const void* p) {
    uint32_t a;
    asm("{ .reg .u64 t; cvta.to.shared.u64 t, %1; cvt.u32.u64 %0, t; }" : "=r"(a) : "l"(p));
    return a;
}
__device__ __forceinline__ void cpasync16(uint32_t dst, const void* src) {
    asm volatile("cp.async.cg.shared.global [%0], [%1], 16;" :: "r"(dst), "l"(src));
}
__device__ __forceinline__ void ldsm4(uint32_t* r, uint32_t a) {
    asm volatile("ldmatrix.sync.aligned.m8n8.x4.shared.b16 {%0,%1,%2,%3}, [%4];"
                 : "=r"(r[0]), "=r"(r[1]), "=r"(r[2]), "=r"(r[3]) : "r"(a));
}
__device__ __forceinline__ void mma16816(float* d, const uint32_t* a, uint32_t b0, uint32_t b1) {
    asm volatile(
        "mma.sync.aligned.m16n8k16.row.col.f32.f16.f16.f32 "
        "{%0,%1,%2,%3},{%4,%5,%6,%7},{%8,%9},{%0,%1,%2,%3};"
        : "+f"(d[0]), "+f"(d[1]), "+f"(d[2]), "+f"(d[3])
        : "r"(a[0]), "r"(a[1]), "r"(a[2]), "r"(a[3]), "r"(b0), "r"(b1));
}
__device__ __forceinline__ float dot4(float4 a, float4 b) {
    return a.x * b.x + a.y * b.y + a.z * b.z + a.w * b.w;
}

// ---------------- 0) convert both weight matrices to fp16 ----------------
__global__ __launch_bounds__(256) void conv_both(const float* __restrict__ wq,
                                                 const float* __restrict__ wp) {
    int i4 = blockIdx.x * 256 + threadIdx.x;
    constexpr int NQ4 = C3 * CC / 4;
    constexpr int NP4 = CC * CC / 4;
    const float4* src;
    __half* h;
    int idx;
    if (i4 < NQ4) { src = (const float4*)wq; h = g_wqh; idx = i4; }
    else if (i4 < NQ4 + NP4) { src = (const float4*)wp; h = g_wph; idx = i4 - NQ4; }
    else return;
    float4 v = src[idx];
    __half hh[4] = {__float2half(v.x), __float2half(v.y), __float2half(v.z), __float2half(v.w)};
    uint2 uh;
    uh.x = *(uint32_t*)&hh[0]; uh.y = *(uint32_t*)&hh[2];
    *(uint2*)(h + idx * 4) = uh;
}

// ---------------- 1) group-norm statistics ----------------
__global__ __launch_bounds__(1024) void gn_stats(const float* __restrict__ x) {
    int bg = blockIdx.x;
    int b  = bg >> 5;
    int g  = bg & 31;
    int hw = threadIdx.x;
    float sum = 0.f, sq = 0.f;
    const float* base = x + ((size_t)b * CC + (size_t)g * CPG) * TT * HWc + hw;
    #pragma unroll 4
    for (int ct = 0; ct < CPG * TT; ct++) {
        float v = base[(size_t)ct * HWc];
        sum += v; sq += v * v;
    }
    float m   = sum * (1.0f / 256.0f);
    float var = sq  * (1.0f / 256.0f) - m * m;
    g_mean[(size_t)bg * HWc + hw] = m;
    g_rstd[(size_t)bg * HWc + hw] = rsqrtf(var + EPSF);
}

// ---------------- 2) normalize + transpose to fp16 [M,512] ----------------
__global__ __launch_bounds__(256) void norm_tr(const float* __restrict__ x,
                                               const float* __restrict__ gamma,
                                               const float* __restrict__ beta) {
    __shared__ float tile[32][33];
    int bx  = blockIdx.x;
    int hwt = bx & 31;
    int ct  = (bx >> 5) & 15;
    int t   = (bx >> 9) & 15;
    int b   = bx >> 13;
    int tid = threadIdx.x;
    {
        int hw_l = tid & 31;
        int c_l0 = tid >> 5;
        int hw   = hwt * 32 + hw_l;
        #pragma unroll
        for (int p = 0; p < 4; p++) {
            int c_l = c_l0 + p * 8;
            int c   = ct * 32 + c_l;
            int g   = c >> 4;
            float v = x[(((size_t)b * CC + c) * TT + t) * HWc + hw];
            size_t si = ((size_t)(b * GRP + g)) * HWc + hw;
            v = (v - g_mean[si]) * g_rstd[si] * gamma[c] + beta[c];
            tile[c_l][hw_l] = v;
        }
    }
    __syncthreads();
    {
        int c2    = (tid & 15) * 2;
        int hw_l0 = tid >> 4;
        #pragma unroll
        for (int p = 0; p < 2; p++) {
            int hw_l = hw_l0 + p * 16;
            int hw   = hwt * 32 + hw_l;
            size_t m = ((size_t)(b * HWc + hw)) * TT + t;
            float v0 = tile[c2][hw_l];
            float v1 = tile[c2 + 1][hw_l];
            size_t idx = m * CC + ct * 32 + c2;
            *(__half2*)(g_nh + idx) = __halves2half2(__float2half(v0), __float2half(v1));
        }
    }
}

// ---------------- HMMA GEMM: single-pass fp16, 3-stage pipeline, templated out ----------------
constexpr int PITCH   = 80;
constexpr int TILE_B  = 128 * PITCH;   // 10240
constexpr int STAGE_B = 2 * TILE_B;    // 20480 (A, B)
constexpr int GEMM_SMEM = 3 * STAGE_B; // 61440

template <bool HALF_OUT>
__global__ __launch_bounds__(256, 2) void hmma_gemm(const __half* __restrict__ A,
                                                    const __half* __restrict__ B,
                                                    const float* __restrict__ bias,
                                                    void* __restrict__ CoutV, int ldc) {
    extern __shared__ char smem[];
    uint32_t sb = smem_u32(smem);
    int tid = threadIdx.x;
    int n0 = blockIdx.x * 128;
    int m0 = blockIdx.y * 128;

    int r = tid >> 2;
    int c = tid & 3;
    const int4* pA = (const int4*)A + (size_t)(m0 + r) * 64 + c;
    const int4* pB = (const int4*)B + (size_t)(n0 + r) * 64 + c;
    uint32_t d0 = sb + r * PITCH + c * 16;
    constexpr int RSTEP = 64 * 64;
    constexpr int DSTEP = 64 * PITCH;

    auto issue = [&](int kk, int stage) {
        uint32_t dst = d0 + stage * STAGE_B;
        int ko = kk * 4;
        cpasync16(dst,                   pA + ko);
        cpasync16(dst + DSTEP,           pA + ko + RSTEP);
        cpasync16(dst + TILE_B,          pB + ko);
        cpasync16(dst + TILE_B + DSTEP,  pB + ko + RSTEP);
        asm volatile("cp.async.commit_group;");
    };

    float acc[4][4][4];
    #pragma unroll
    for (int a = 0; a < 4; a++)
        #pragma unroll
        for (int b = 0; b < 4; b++)
            #pragma unroll
            for (int cc = 0; cc < 4; cc++) acc[a][b][cc] = 0.f;

    int wid = tid >> 5, lane = tid & 31;
    int mw  = (wid >> 2) * 64;
    int nwv = (wid & 3) * 32;
    int lrow = lane & 15;
    int lk   = (lane >> 4) * 16;
    uint32_t adab = (mw + lrow) * PITCH + lk;
    uint32_t bdab = TILE_B + (nwv + lrow) * PITCH + lk;

    issue(0, 0);
    issue(1, 1);

    #pragma unroll 1
    for (int ks = 0; ks < 16; ks++) {
        if (ks < 15) asm volatile("cp.async.wait_group 1;");
        else         asm volatile("cp.async.wait_group 0;");
        __syncthreads();
        if (ks + 2 < 16) issue(ks + 2, (ks + 2) % 3);

        uint32_t sa = sb + (ks % 3) * STAGE_B;
        #pragma unroll
        for (int j = 0; j < 2; j++) {
            uint32_t am[4][4], bm[2][4];
            #pragma unroll
            for (int mt = 0; mt < 4; mt++)
                ldsm4(am[mt], sa + adab + mt * (16 * PITCH) + j * 32);
            #pragma unroll
            for (int bt = 0; bt < 2; bt++)
                ldsm4(bm[bt], sa + bdab + bt * (16 * PITCH) + j * 32);
            #pragma unroll
            for (int mt = 0; mt < 4; mt++)
                #pragma unroll
                for (int nt = 0; nt < 4; nt++) {
                    int bt = nt >> 1, s = nt & 1;
                    mma16816(acc[mt][nt], am[mt], bm[bt][s], bm[bt][2 + s]);
                }
        }
    }

    int row_in = lane >> 2;
    int colq   = (lane & 3) * 2;
    #pragma unroll
    for (int mt = 0; mt < 4; mt++) {
        int gr = m0 + mw + mt * 16 + row_in;
        #pragma unroll
        for (int nt = 0; nt < 4; nt++) {
            int gc = n0 + nwv + nt * 8 + colq;
            float b0 = bias[gc], b1 = bias[gc + 1];
            float o00 = acc[mt][nt][0] + b0, o01 = acc[mt][nt][1] + b1;
            float o10 = acc[mt][nt][2] + b0, o11 = acc[mt][nt][3] + b1;
            if (HALF_OUT) {
                __half* C = (__half*)CoutV;
                *(__half2*)(C + (size_t)gr * ldc + gc) =
                    __halves2half2(__float2half(o00), __float2half(o01));
                *(__half2*)(C + (size_t)(gr + 8) * ldc + gc) =
                    __halves2half2(__float2half(o10), __float2half(o11));
            } else {
                float* C = (float*)CoutV;
                *(float2*)(C + (size_t)gr * ldc + gc)       = make_float2(o00, o01);
                *(float2*)(C + (size_t)(gr + 8) * ldc + gc) = make_float2(o10, o11);
            }
        }
    }
}

// ---------------- 4) attention: one block per n, all 8 heads ----------------
constexpr int QP = 516;
constexpr int RP = 68;
constexpr int OFF_Q  = 0;
constexpr int OFF_K  = 16 * QP;
constexpr int OFF_V  = 32 * QP;
constexpr int OFF_RK = 48 * QP;
constexpr int OFF_RV = OFF_RK + 31 * RP;
constexpr int OFF_WS = OFF_RV + 31 * RP;
constexpr int ATTN_SMEM = (OFF_WS + 8 * 16 * 17) * 4;

__global__ __launch_bounds__(256, 1) void attn(const float* __restrict__ rp_k,
                                               const float* __restrict__ rp_v) {
    extern __shared__ float sm[];
    float* q  = sm + OFF_Q;
    float* k  = sm + OFF_K;
    float* v  = sm + OFF_V;
    float* rk = sm + OFF_RK;
    float* rv = sm + OFF_RV;
    float* ws = sm + OFF_WS;

    int n   = blockIdx.x;
    int tid = threadIdx.x;
    const float scale = 0.35355339059327373f;

    // load fp16 qkv: 16 rows x 192 uint4 (8 halves each) per n
    const uint4* gq = reinterpret_cast<const uint4*>(g_qkv);
    #pragma unroll
    for (int it = 0; it < 12; it++) {
        int idx = it * 256 + tid;          // 0..3071
        int t   = idx / 192;
        int rem = idx - t * 192;
        int which = rem >> 6;              // 0=q 1=k 2=v
        int c8    = rem & 63;
        uint4 raw = gq[(size_t)(n * TT + t) * 192 + rem];
        __half2* hp = (__half2*)&raw;
        float2 f0 = __half22float2(hp[0]);
        float2 f1 = __half22float2(hp[1]);
        float2 f2 = __half22float2(hp[2]);
        float2 f3 = __half22float2(hp[3]);
        if (which < 2) {
            f0.x *= scale; f0.y *= scale; f1.x *= scale; f1.y *= scale;
            f2.x *= scale; f2.y *= scale; f3.x *= scale; f3.y *= scale;
        }
        float* dst = (which == 0 ? q : which == 1 ? k : v) + t * QP + c8 * 8;
        *(float4*)(dst)     = make_float4(f0.x, f0.y, f1.x, f1.y);
        *(float4*)(dst + 4) = make_float4(f2.x, f2.y, f3.x, f3.y);
    }
    const float4* grk = reinterpret_cast<const float4*>(rp_k);
    const float4* grv = reinterpret_cast<const float4*>(rp_v);
    for (int idx = tid; idx < 992; idx += 256) {
        int half = idx >= 496;
        int r = idx - half * 496;
        int row = r >> 4, c4 = r & 15;
        float4 val = (half ? grv : grk)[(49 + row) * 16 + c4];
        *(float4*)((half ? rv : rk) + row * RP + c4 * 4) = val;
    }
    __syncthreads();

    {
        int h = tid >> 5;
        int r5 = tid & 31;
        int tile = r5 & 15;
        int chalf = r5 >> 4;
        int ti = (tile >> 2) << 2;
        int tj = (tile & 3) << 2;
        int cbase = h * 64 + chalf * 32;
        const float* rkb = rk + (ti - tj + 12) * RP + chalf * 32;

        float acc[4][4];
        #pragma unroll
        for (int a = 0; a < 4; a++)
            #pragma unroll
            for (int b = 0; b < 4; b++) acc[a][b] = 0.f;

        #pragma unroll
        for (int c4 = 0; c4 < 8; c4++) {
            int c = cbase + c4 * 4;
            float4 qi[4], kj[4], qj[4], rr[7];
            #pragma unroll
            for (int a = 0; a < 4; a++) qi[a] = *(const float4*)(q + (ti + a) * QP + c);
            #pragma unroll
            for (int b = 0; b < 4; b++) {
                kj[b] = *(const float4*)(k + (tj + b) * QP + c);
                qj[b] = *(const float4*)(q + (tj + b) * QP + c);
            }
            #pragma unroll
            for (int e = 0; e < 7; e++) rr[e] = *(const float4*)(rkb + e * RP + c4 * 4);
            #pragma unroll
            for (int a = 0; a < 4; a++)
                #pragma unroll
                for (int b = 0; b < 4; b++)
                    acc[a][b] += dot4(qi[a], kj[b]) + dot4(qj[b], rr[a - b + 3]);
        }
        #pragma unroll
        for (int a = 0; a < 4; a++)
            #pragma unroll
            for (int b = 0; b < 4; b++) {
                acc[a][b] += __shfl_xor_sync(0xFFFFFFFFu, acc[a][b], 16);
                if (chalf == 0) ws[h * 272 + (ti + a) * 17 + tj + b] = acc[a][b];
            }
    }
    __syncthreads();

    if (tid < 128) {
        int h = tid >> 4, i = tid & 15;
        float* wp = ws + h * 272 + i * 17;
        float mx = -1e30f;
        #pragma unroll
        for (int j = 0; j < 16; j++) mx = fmaxf(mx, wp[j]);
        float e[16]; float sum = 0.f;
        #pragma unroll
        for (int j = 0; j < 16; j++) { e[j] = __expf(wp[j] - mx); sum += e[j]; }
        float inv = 1.f / sum;
        #pragma unroll
        for (int j = 0; j < 16; j++) wp[j] = e[j] * inv;
    }
    __syncthreads();

    {
        int h = tid >> 5;
        int r5 = tid & 31;
        int tgrp = r5 >> 3;
        int cq = r5 & 7;
        int t0 = tgrp * 4;
        int c = h * 64 + cq * 8;
        const float* wsb = ws + h * 272;

        float acc[4][8];
        #pragma unroll
        for (int t = 0; t < 4; t++)
            #pragma unroll
            for (int j = 0; j < 8; j++) acc[t][j] = 0.f;

        #pragma unroll
        for (int s = 0; s < 16; s++) {
            float4 v0 = *(const float4*)(v + s * QP + c);
            float4 v1 = *(const float4*)(v + s * QP + c + 4);
            #pragma unroll
            for (int t = 0; t < 4; t++) {
                float wv = wsb[(t0 + t) * 17 + s];
                acc[t][0] += wv * v0.x; acc[t][1] += wv * v0.y;
                acc[t][2] += wv * v0.z; acc[t][3] += wv * v0.w;
                acc[t][4] += wv * v1.x; acc[t][5] += wv * v1.y;
                acc[t][6] += wv * v1.z; acc[t][7] += wv * v1.w;
            }
        }
        #pragma unroll
        for (int d = 0; d < 31; d++) {
            float4 r0 = *(const float4*)(rv + d * RP + cq * 8);
            float4 r1 = *(const float4*)(rv + d * RP + cq * 8 + 4);
            #pragma unroll
            for (int t = 0; t < 4; t++) {
                int s = d + t0 + t - 15;
                if (s >= 0 && s < 16) {
                    float wv = wsb[(t0 + t) * 17 + s];
                    acc[t][0] += wv * r0.x; acc[t][1] += wv * r0.y;
                    acc[t][2] += wv * r0.z; acc[t][3] += wv * r0.w;
                    acc[t][4] += wv * r1.x; acc[t][5] += wv * r1.y;
                    acc[t][6] += wv * r1.z; acc[t][7] += wv * r1.w;
                }
            }
        }
        #pragma unroll
        for (int t = 0; t < 4; t++) {
            size_t idx = ((size_t)(n * TT + t0 + t)) * CC + c;
            uint4 uh;
            __half hh[8];
            #pragma unroll
            for (int j = 0; j < 8; j++) hh[j] = __float2half(acc[t][j]);
            uh.x = *(uint32_t*)&hh[0]; uh.y = *(uint32_t*)&hh[2];
            uh.z = *(uint32_t*)&hh[4]; uh.w = *(uint32_t*)&hh[6];
            *(uint4*)(g_ah + idx) = uh;
        }
    }
}

// ---------------- 6) transpose back + residual ----------------
__global__ __launch_bounds__(256) void resid_tr(const float* __restrict__ x,
                                                float* __restrict__ out) {
    __shared__ float tile[32][33];
    int bx  = blockIdx.x;
    int hwt = bx & 31;
    int ct  = (bx >> 5) & 15;
    int t   = (bx >> 9) & 15;
    int b   = bx >> 13;
    int tid = threadIdx.x;
    {
        int c_l   = tid & 31;
        int hw_l0 = tid >> 5;
        #pragma unroll
        for (int p = 0; p < 4; p++) {
            int hw_l = hw_l0 + p * 8;
            int hw   = hwt * 32 + hw_l;
            size_t m = ((size_t)(b * HWc + hw)) * TT + t;
            tile[hw_l][c_l] = g_pout[m * CC + ct * 32 + c_l];
        }
    }
    __syncthreads();
    {
        int hw_l = tid & 31;
        int c_l0 = tid >> 5;
        int hw   = hwt * 32 + hw_l;
        #pragma unroll
        for (int p = 0; p < 4; p++) {
            int c_l = c_l0 + p * 8;
            int c   = ct * 32 + c_l;
            size_t idx = (((size_t)b * CC + c) * TT + t) * HWc + hw;
            out[idx] = x[idx] + tile[hw_l][c_l];
        }
    }
}

// ---------------- host launch ----------------
extern "C" void kernel_launch(void* const* d_in, const int* in_sizes, int n_in,
                              void* d_out, int out_size) {
    const float* x      = (const float*)d_in[0];
    const float* gamma  = (const float*)d_in[1];
    const float* beta   = (const float*)d_in[2];
    const float* w_qkv  = (const float*)d_in[3];
    const float* b_qkv  = (const float*)d_in[4];
    const float* rp_k   = (const float*)d_in[5];
    const float* rp_v   = (const float*)d_in[6];
    const float* w_proj = (const float*)d_in[7];
    const float* b_proj = (const float*)d_in[8];
    float* out = (float*)d_out;

    cudaFuncSetAttribute(hmma_gemm<true>,  cudaFuncAttributeMaxDynamicSharedMemorySize, GEMM_SMEM);
    cudaFuncSetAttribute(hmma_gemm<false>, cudaFuncAttributeMaxDynamicSharedMemorySize, GEMM_SMEM);
    cudaFuncSetAttribute(attn, cudaFuncAttributeMaxDynamicSharedMemorySize, ATTN_SMEM);

    __half *wqh, *wph, *nh, *ah, *qkv;
    cudaGetSymbolAddress((void**)&wqh, g_wqh);
    cudaGetSymbolAddress((void**)&wph, g_wph);
    cudaGetSymbolAddress((void**)&nh, g_nh);
    cudaGetSymbolAddress((void**)&ah, g_ah);
    cudaGetSymbolAddress((void**)&qkv, g_qkv);
    float *pout;
    cudaGetSymbolAddress((void**)&pout, g_pout);

    // hmma_gemm(qkv) stays launch #4 for ncu attribution
    conv_both<<<(C3 * CC / 4 + CC * CC / 4 + 255) / 256, 256>>>(w_qkv, w_proj);
    gn_stats<<<BB * GRP, 1024>>>(x);
    norm_tr<<<BB * TT * (CC / 32) * (HWc / 32), 256>>>(x, gamma, beta);
    hmma_gemm<true><<<dim3(C3 / 128, MM / 128), 256, GEMM_SMEM>>>(nh, wqh, b_qkv, qkv, C3);
    attn<<<NN, 256, ATTN_SMEM>>>(rp_k, rp_v);
    hmma_gemm<false><<<dim3(CC / 128, MM / 128), 256, GEMM_SMEM>>>(ah, wph, b_proj, pout, CC);
    resid_tr<<<BB * TT * (CC / 32) * (HWc / 32), 256>>>(x, out);
}

// round 10
// speedup vs baseline: 1.0678x; 1.0678x over previous
#include <cuda_runtime.h>
#include <cuda_fp16.h>
#include <stdint.h>
#include <math.h>

// ---------------- problem constants ----------------
constexpr int BB   = 4;
constexpr int CC   = 512;
constexpr int TT   = 16;
constexpr int HWc  = 1024;
constexpr int NN   = BB * HWc;      // 4096
constexpr int MM   = NN * TT;       // 65536
constexpr int NH   = 8;
constexpr int CH   = 64;
constexpr int GRP  = 32;
constexpr int CPG  = CC / GRP;      // 16
constexpr int C3   = 3 * CC;        // 1536
constexpr float EPSF = 1e-6f;

// ---------------- scratch (static device globals) ----------------
__device__ float g_mean[BB * GRP * HWc];
__device__ float g_rstd[BB * GRP * HWc];
__device__ __half g_nh[(size_t)MM * CC];    // normed activations (fp16)
__device__ __half g_wqh[C3 * CC];           // qkv weights (fp16)
__device__ __half g_wph[CC * CC];           // proj weights (fp16)
__device__ __half g_qkv[(size_t)MM * C3];   // qkv output (fp16)
__device__ __half g_ah[(size_t)MM * CC];    // attention out (fp16)
__device__ float g_pout[(size_t)MM * CC];

// ---------------- helpers ----------------
__device__ __forceinline__ uint32_t smem_u32(const void* p) {
    uint32_t a;
    asm("{ .reg .u64 t; cvta.to.shared.u64 t, %1; cvt.u32.u64 %0, t; }" : "=r"(a) : "l"(p));
    return a;
}
__device__ __forceinline__ void cpasync16(uint32_t dst, const void* src) {
    asm volatile("cp.async.cg.shared.global [%0], [%1], 16;" :: "r"(dst), "l"(src));
}
__device__ __forceinline__ void ldsm4(uint32_t* r, uint32_t a) {
    asm volatile("ldmatrix.sync.aligned.m8n8.x4.shared.b16 {%0,%1,%2,%3}, [%4];"
                 : "=r"(r[0]), "=r"(r[1]), "=r"(r[2]), "=r"(r[3]) : "r"(a));
}
__device__ __forceinline__ void mma16816(float* d, const uint32_t* a, uint32_t b0, uint32_t b1) {
    asm volatile(
        "mma.sync.aligned.m16n8k16.row.col.f32.f16.f16.f32 "
        "{%0,%1,%2,%3},{%4,%5,%6,%7},{%8,%9},{%0,%1,%2,%3};"
        : "+f"(d[0]), "+f"(d[1]), "+f"(d[2]), "+f"(d[3])
        : "r"(a[0]), "r"(a[1]), "r"(a[2]), "r"(a[3]), "r"(b0), "r"(b1));
}
__device__ __forceinline__ float dot4(float4 a, float4 b) {
    return a.x * b.x + a.y * b.y + a.z * b.z + a.w * b.w;
}

// ---------------- 0) convert both weight matrices to fp16 ----------------
__global__ __launch_bounds__(256) void conv_both(const float* __restrict__ wq,
                                                 const float* __restrict__ wp) {
    int i4 = blockIdx.x * 256 + threadIdx.x;
    constexpr int NQ4 = C3 * CC / 4;
    constexpr int NP4 = CC * CC / 4;
    const float4* src;
    __half* h;
    int idx;
    if (i4 < NQ4) { src = (const float4*)wq; h = g_wqh; idx = i4; }
    else if (i4 < NQ4 + NP4) { src = (const float4*)wp; h = g_wph; idx = i4 - NQ4; }
    else return;
    float4 v = src[idx];
    __half hh[4] = {__float2half(v.x), __float2half(v.y), __float2half(v.z), __float2half(v.w)};
    uint2 uh;
    uh.x = *(uint32_t*)&hh[0]; uh.y = *(uint32_t*)&hh[2];
    *(uint2*)(h + idx * 4) = uh;
}

// ---------------- 1) group-norm statistics ----------------
__global__ __launch_bounds__(1024) void gn_stats(const float* __restrict__ x) {
    int bg = blockIdx.x;
    int b  = bg >> 5;
    int g  = bg & 31;
    int hw = threadIdx.x;
    float sum = 0.f, sq = 0.f;
    const float* base = x + ((size_t)b * CC + (size_t)g * CPG) * TT * HWc + hw;
    #pragma unroll 4
    for (int ct = 0; ct < CPG * TT; ct++) {
        float v = base[(size_t)ct * HWc];
        sum += v; sq += v * v;
    }
    float m   = sum * (1.0f / 256.0f);
    float var = sq  * (1.0f / 256.0f) - m * m;
    g_mean[(size_t)bg * HWc + hw] = m;
    g_rstd[(size_t)bg * HWc + hw] = rsqrtf(var + EPSF);
}

// ---------------- 2) normalize + transpose to fp16 [M,512] ----------------
__global__ __launch_bounds__(256) void norm_tr(const float* __restrict__ x,
                                               const float* __restrict__ gamma,
                                               const float* __restrict__ beta) {
    __shared__ float tile[32][33];
    int bx  = blockIdx.x;
    int hwt = bx & 31;
    int ct  = (bx >> 5) & 15;
    int t   = (bx >> 9) & 15;
    int b   = bx >> 13;
    int tid = threadIdx.x;
    {
        int hw_l = tid & 31;
        int c_l0 = tid >> 5;
        int hw   = hwt * 32 + hw_l;
        #pragma unroll
        for (int p = 0; p < 4; p++) {
            int c_l = c_l0 + p * 8;
            int c   = ct * 32 + c_l;
            int g   = c >> 4;
            float v = x[(((size_t)b * CC + c) * TT + t) * HWc + hw];
            size_t si = ((size_t)(b * GRP + g)) * HWc + hw;
            v = (v - g_mean[si]) * g_rstd[si] * gamma[c] + beta[c];
            tile[c_l][hw_l] = v;
        }
    }
    __syncthreads();
    {
        int c2    = (tid & 15) * 2;
        int hw_l0 = tid >> 4;
        #pragma unroll
        for (int p = 0; p < 2; p++) {
            int hw_l = hw_l0 + p * 16;
            int hw   = hwt * 32 + hw_l;
            size_t m = ((size_t)(b * HWc + hw)) * TT + t;
            float v0 = tile[c2][hw_l];
            float v1 = tile[c2 + 1][hw_l];
            size_t idx = m * CC + ct * 32 + c2;
            *(__half2*)(g_nh + idx) = __halves2half2(__float2half(v0), __float2half(v1));
        }
    }
}

// ---------------- HMMA GEMM: fragment-prefetch pipeline, 4-stage smem ring ----------------
constexpr int PITCH   = 80;
constexpr int TILE_B  = 128 * PITCH;   // 10240
constexpr int STAGE_B = 2 * TILE_B;    // 20480 (A, B)
constexpr int GEMM_SMEM = 4 * STAGE_B; // 81920

template <bool HALF_OUT>
__global__ __launch_bounds__(256, 2) void hmma_gemm(const __half* __restrict__ A,
                                                    const __half* __restrict__ B,
                                                    const float* __restrict__ bias,
                                                    void* __restrict__ CoutV, int ldc) {
    extern __shared__ char smem[];
    uint32_t sb = smem_u32(smem);
    int tid = threadIdx.x;
    int n0 = blockIdx.x * 128;
    int m0 = blockIdx.y * 128;

    int r = tid >> 2;
    int c = tid & 3;
    const int4* pA = (const int4*)A + (size_t)(m0 + r) * 64 + c;
    const int4* pB = (const int4*)B + (size_t)(n0 + r) * 64 + c;
    uint32_t d0 = sb + r * PITCH + c * 16;
    constexpr int RSTEP = 64 * 64;
    constexpr int DSTEP = 64 * PITCH;

    auto issue = [&](int kk, int stage) {
        uint32_t dst = d0 + stage * STAGE_B;
        int ko = kk * 4;
        cpasync16(dst,                   pA + ko);
        cpasync16(dst + DSTEP,           pA + ko + RSTEP);
        cpasync16(dst + TILE_B,          pB + ko);
        cpasync16(dst + TILE_B + DSTEP,  pB + ko + RSTEP);
        asm volatile("cp.async.commit_group;");
    };

    float acc[4][4][4];
    #pragma unroll
    for (int a = 0; a < 4; a++)
        #pragma unroll
        for (int b = 0; b < 4; b++)
            #pragma unroll
            for (int cc = 0; cc < 4; cc++) acc[a][b][cc] = 0.f;

    int wid = tid >> 5, lane = tid & 31;
    int mw  = (wid >> 2) * 64;
    int nwv = (wid & 3) * 32;
    int lrow = lane & 15;
    int lk   = (lane >> 4) * 16;
    uint32_t adab = (mw + lrow) * PITCH + lk;
    uint32_t bdab = TILE_B + (nwv + lrow) * PITCH + lk;

    // fragment double buffers
    uint32_t amA[4][4], bmA[2][4];   // even phases
    uint32_t amB[4][4], bmB[2][4];   // odd phases

    auto load_frags = [&](uint32_t am[4][4], uint32_t bm[2][4], uint32_t sa, int j) {
        #pragma unroll
        for (int mt = 0; mt < 4; mt++)
            ldsm4(am[mt], sa + adab + mt * (16 * PITCH) + j * 32);
        #pragma unroll
        for (int bt = 0; bt < 2; bt++)
            ldsm4(bm[bt], sa + bdab + bt * (16 * PITCH) + j * 32);
    };
    auto mma_all = [&](uint32_t am[4][4], uint32_t bm[2][4]) {
        #pragma unroll
        for (int mt = 0; mt < 4; mt++)
            #pragma unroll
            for (int nt = 0; nt < 4; nt++) {
                int bt = nt >> 1, s = nt & 1;
                mma16816(acc[mt][nt], am[mt], bm[bt][s], bm[bt][2 + s]);
            }
    };

    issue(0, 0);
    issue(1, 1);
    issue(2, 2);
    asm volatile("cp.async.wait_group 2;");
    __syncthreads();
    load_frags(amA, bmA, sb, 0);        // (ks=0, j=0) from stage 0

    #pragma unroll 1
    for (int ks = 0; ks < 16; ks++) {
        // guarantee stage ks+1 arrived (needed by the j=1 phase's prefetch)
        if (ks < 14) asm volatile("cp.async.wait_group 1;");
        else         asm volatile("cp.async.wait_group 0;");
        __syncthreads();
        if (ks + 3 < 16) issue(ks + 3, (ks + 3) & 3);

        uint32_t sa  = sb + (ks & 3) * STAGE_B;
        uint32_t san = sb + ((ks + 1) & 3) * STAGE_B;

        // phase j=0: prefetch (ks, j=1), compute (ks, j=0)
        load_frags(amB, bmB, sa, 1);
        mma_all(amA, bmA);
        // phase j=1: prefetch (ks+1, j=0), compute (ks, j=1)
        if (ks < 15) load_frags(amA, bmA, san, 0);
        mma_all(amB, bmB);
    }

    int row_in = lane >> 2;
    int colq   = (lane & 3) * 2;
    #pragma unroll
    for (int mt = 0; mt < 4; mt++) {
        int gr = m0 + mw + mt * 16 + row_in;
        #pragma unroll
        for (int nt = 0; nt < 4; nt++) {
            int gc = n0 + nwv + nt * 8 + colq;
            float b0 = bias[gc], b1 = bias[gc + 1];
            float o00 = acc[mt][nt][0] + b0, o01 = acc[mt][nt][1] + b1;
            float o10 = acc[mt][nt][2] + b0, o11 = acc[mt][nt][3] + b1;
            if (HALF_OUT) {
                __half* C = (__half*)CoutV;
                *(__half2*)(C + (size_t)gr * ldc + gc) =
                    __halves2half2(__float2half(o00), __float2half(o01));
                *(__half2*)(C + (size_t)(gr + 8) * ldc + gc) =
                    __halves2half2(__float2half(o10), __float2half(o11));
            } else {
                float* C = (float*)CoutV;
                *(float2*)(C + (size_t)gr * ldc + gc)       = make_float2(o00, o01);
                *(float2*)(C + (size_t)(gr + 8) * ldc + gc) = make_float2(o10, o11);
            }
        }
    }
}

// ---------------- 4) attention: one block per n, all 8 heads ----------------
constexpr int QP = 516;
constexpr int RP = 68;
constexpr int OFF_Q  = 0;
constexpr int OFF_K  = 16 * QP;
constexpr int OFF_V  = 32 * QP;
constexpr int OFF_RK = 48 * QP;
constexpr int OFF_RV = OFF_RK + 31 * RP;
constexpr int OFF_WS = OFF_RV + 31 * RP;
constexpr int ATTN_SMEM = (OFF_WS + 8 * 16 * 17) * 4;

__global__ __launch_bounds__(256, 1) void attn(const float* __restrict__ rp_k,
                                               const float* __restrict__ rp_v) {
    extern __shared__ float sm[];
    float* q  = sm + OFF_Q;
    float* k  = sm + OFF_K;
    float* v  = sm + OFF_V;
    float* rk = sm + OFF_RK;
    float* rv = sm + OFF_RV;
    float* ws = sm + OFF_WS;

    int n   = blockIdx.x;
    int tid = threadIdx.x;
    const float scale = 0.35355339059327373f;

    const uint4* gq = reinterpret_cast<const uint4*>(g_qkv);
    #pragma unroll
    for (int it = 0; it < 12; it++) {
        int idx = it * 256 + tid;
        int t   = idx / 192;
        int rem = idx - t * 192;
        int which = rem >> 6;
        int c8    = rem & 63;
        uint4 raw = gq[(size_t)(n * TT + t) * 192 + rem];
        __half2* hp = (__half2*)&raw;
        float2 f0 = __half22float2(hp[0]);
        float2 f1 = __half22float2(hp[1]);
        float2 f2 = __half22float2(hp[2]);
        float2 f3 = __half22float2(hp[3]);
        if (which < 2) {
            f0.x *= scale; f0.y *= scale; f1.x *= scale; f1.y *= scale;
            f2.x *= scale; f2.y *= scale; f3.x *= scale; f3.y *= scale;
        }
        float* dst = (which == 0 ? q : which == 1 ? k : v) + t * QP + c8 * 8;
        *(float4*)(dst)     = make_float4(f0.x, f0.y, f1.x, f1.y);
        *(float4*)(dst + 4) = make_float4(f2.x, f2.y, f3.x, f3.y);
    }
    const float4* grk = reinterpret_cast<const float4*>(rp_k);
    const float4* grv = reinterpret_cast<const float4*>(rp_v);
    for (int idx = tid; idx < 992; idx += 256) {
        int half = idx >= 496;
        int r = idx - half * 496;
        int row = r >> 4, c4 = r & 15;
        float4 val = (half ? grv : grk)[(49 + row) * 16 + c4];
        *(float4*)((half ? rv : rk) + row * RP + c4 * 4) = val;
    }
    __syncthreads();

    {
        int h = tid >> 5;
        int r5 = tid & 31;
        int tile = r5 & 15;
        int chalf = r5 >> 4;
        int ti = (tile >> 2) << 2;
        int tj = (tile & 3) << 2;
        int cbase = h * 64 + chalf * 32;
        const float* rkb = rk + (ti - tj + 12) * RP + chalf * 32;

        float acc[4][4];
        #pragma unroll
        for (int a = 0; a < 4; a++)
            #pragma unroll
            for (int b = 0; b < 4; b++) acc[a][b] = 0.f;

        #pragma unroll
        for (int c4 = 0; c4 < 8; c4++) {
            int c = cbase + c4 * 4;
            float4 qi[4], kj[4], qj[4], rr[7];
            #pragma unroll
            for (int a = 0; a < 4; a++) qi[a] = *(const float4*)(q + (ti + a) * QP + c);
            #pragma unroll
            for (int b = 0; b < 4; b++) {
                kj[b] = *(const float4*)(k + (tj + b) * QP + c);
                qj[b] = *(const float4*)(q + (tj + b) * QP + c);
            }
            #pragma unroll
            for (int e = 0; e < 7; e++) rr[e] = *(const float4*)(rkb + e * RP + c4 * 4);
            #pragma unroll
            for (int a = 0; a < 4; a++)
                #pragma unroll
                for (int b = 0; b < 4; b++)
                    acc[a][b] += dot4(qi[a], kj[b]) + dot4(qj[b], rr[a - b + 3]);
        }
        #pragma unroll
        for (int a = 0; a < 4; a++)
            #pragma unroll
            for (int b = 0; b < 4; b++) {
                acc[a][b] += __shfl_xor_sync(0xFFFFFFFFu, acc[a][b], 16);
                if (chalf == 0) ws[h * 272 + (ti + a) * 17 + tj + b] = acc[a][b];
            }
    }
    __syncthreads();

    if (tid < 128) {
        int h = tid >> 4, i = tid & 15;
        float* wp = ws + h * 272 + i * 17;
        float mx = -1e30f;
        #pragma unroll
        for (int j = 0; j < 16; j++) mx = fmaxf(mx, wp[j]);
        float e[16]; float sum = 0.f;
        #pragma unroll
        for (int j = 0; j < 16; j++) { e[j] = __expf(wp[j] - mx); sum += e[j]; }
        float inv = 1.f / sum;
        #pragma unroll
        for (int j = 0; j < 16; j++) wp[j] = e[j] * inv;
    }
    __syncthreads();

    {
        int h = tid >> 5;
        int r5 = tid & 31;
        int tgrp = r5 >> 3;
        int cq = r5 & 7;
        int t0 = tgrp * 4;
        int c = h * 64 + cq * 8;
        const float* wsb = ws + h * 272;

        float acc[4][8];
        #pragma unroll
        for (int t = 0; t < 4; t++)
            #pragma unroll
            for (int j = 0; j < 8; j++) acc[t][j] = 0.f;

        #pragma unroll
        for (int s = 0; s < 16; s++) {
            float4 v0 = *(const float4*)(v + s * QP + c);
            float4 v1 = *(const float4*)(v + s * QP + c + 4);
            #pragma unroll
            for (int t = 0; t < 4; t++) {
                float wv = wsb[(t0 + t) * 17 + s];
                acc[t][0] += wv * v0.x; acc[t][1] += wv * v0.y;
                acc[t][2] += wv * v0.z; acc[t][3] += wv * v0.w;
                acc[t][4] += wv * v1.x; acc[t][5] += wv * v1.y;
                acc[t][6] += wv * v1.z; acc[t][7] += wv * v1.w;
            }
        }
        #pragma unroll
        for (int d = 0; d < 31; d++) {
            float4 r0 = *(const float4*)(rv + d * RP + cq * 8);
            float4 r1 = *(const float4*)(rv + d * RP + cq * 8 + 4);
            #pragma unroll
            for (int t = 0; t < 4; t++) {
                int s = d + t0 + t - 15;
                if (s >= 0 && s < 16) {
                    float wv = wsb[(t0 + t) * 17 + s];
                    acc[t][0] += wv * r0.x; acc[t][1] += wv * r0.y;
                    acc[t][2] += wv * r0.z; acc[t][3] += wv * r0.w;
                    acc[t][4] += wv * r1.x; acc[t][5] += wv * r1.y;
                    acc[t][6] += wv * r1.z; acc[t][7] += wv * r1.w;
                }
            }
        }
        #pragma unroll
        for (int t = 0; t < 4; t++) {
            size_t idx = ((size_t)(n * TT + t0 + t)) * CC + c;
            uint4 uh;
            __half hh[8];
            #pragma unroll
            for (int j = 0; j < 8; j++) hh[j] = __float2half(acc[t][j]);
            uh.x = *(uint32_t*)&hh[0]; uh.y = *(uint32_t*)&hh[2];
            uh.z = *(uint32_t*)&hh[4]; uh.w = *(uint32_t*)&hh[6];
            *(uint4*)(g_ah + idx) = uh;
        }
    }
}

// ---------------- 6) transpose back + residual ----------------
__global__ __launch_bounds__(256) void resid_tr(const float* __restrict__ x,
                                                float* __restrict__ out) {
    __shared__ float tile[32][33];
    int bx  = blockIdx.x;
    int hwt = bx & 31;
    int ct  = (bx >> 5) & 15;
    int t   = (bx >> 9) & 15;
    int b   = bx >> 13;
    int tid = threadIdx.x;
    {
        int c_l   = tid & 31;
        int hw_l0 = tid >> 5;
        #pragma unroll
        for (int p = 0; p < 4; p++) {
            int hw_l = hw_l0 + p * 8;
            int hw   = hwt * 32 + hw_l;
            size_t m = ((size_t)(b * HWc + hw)) * TT + t;
            tile[hw_l][c_l] = g_pout[m * CC + ct * 32 + c_l];
        }
    }
    __syncthreads();
    {
        int hw_l = tid & 31;
        int c_l0 = tid >> 5;
        int hw   = hwt * 32 + hw_l;
        #pragma unroll
        for (int p = 0; p < 4; p++) {
            int c_l = c_l0 + p * 8;
            int c   = ct * 32 + c_l;
            size_t idx = (((size_t)b * CC + c) * TT + t) * HWc + hw;
            out[idx] = x[idx] + tile[hw_l][c_l];
        }
    }
}

// ---------------- host launch ----------------
extern "C" void kernel_launch(void* const* d_in, const int* in_sizes, int n_in,
                              void* d_out, int out_size) {
    const float* x      = (const float*)d_in[0];
    const float* gamma  = (const float*)d_in[1];
    const float* beta   = (const float*)d_in[2];
    const float* w_qkv  = (const float*)d_in[3];
    const float* b_qkv  = (const float*)d_in[4];
    const float* rp_k   = (const float*)d_in[5];
    const float* rp_v   = (const float*)d_in[6];
    const float* w_proj = (const float*)d_in[7];
    const float* b_proj = (const float*)d_in[8];
    float* out = (float*)d_out;

    cudaFuncSetAttribute(hmma_gemm<true>,  cudaFuncAttributeMaxDynamicSharedMemorySize, GEMM_SMEM);
    cudaFuncSetAttribute(hmma_gemm<false>, cudaFuncAttributeMaxDynamicSharedMemorySize, GEMM_SMEM);
    cudaFuncSetAttribute(attn, cudaFuncAttributeMaxDynamicSharedMemorySize, ATTN_SMEM);

    __half *wqh, *wph, *nh, *ah, *qkv;
    cudaGetSymbolAddress((void**)&wqh, g_wqh);
    cudaGetSymbolAddress((void**)&wph, g_wph);
    cudaGetSymbolAddress((void**)&nh, g_nh);
    cudaGetSymbolAddress((void**)&ah, g_ah);
    cudaGetSymbolAddress((void**)&qkv, g_qkv);
    float *pout;
    cudaGetSymbolAddress((void**)&pout, g_pout);

    // hmma_gemm(qkv) stays launch #4 for ncu attribution
    conv_both<<<(C3 * CC / 4 + CC * CC / 4 + 255) / 256, 256>>>(w_qkv, w_proj);
    gn_stats<<<BB * GRP, 1024>>>(x);
    norm_tr<<<BB * TT * (CC / 32) * (HWc / 32), 256>>>(x, gamma, beta);
    hmma_gemm<true><<<dim3(C3 / 128, MM / 128), 256, GEMM_SMEM>>>(nh, wqh, b_qkv, qkv, C3);
    attn<<<NN, 256, ATTN_SMEM>>>(rp_k, rp_v);
    hmma_gemm<false><<<dim3(CC / 128, MM / 128), 256, GEMM_SMEM>>>(ah, wph, b_proj, pout, CC);
    resid_tr<<<BB * TT * (CC / 32) * (HWc / 32), 256>>>(x, out);
}

// round 11
// speedup vs baseline: 1.2290x; 1.1509x over previous
#include <cuda_runtime.h>
#include <cuda_fp16.h>
#include <stdint.h>
#include <math.h>

// ---------------- problem constants ----------------
constexpr int BB   = 4;
constexpr int CC   = 512;
constexpr int TT   = 16;
constexpr int HWc  = 1024;
constexpr int NN   = BB * HWc;      // 4096
constexpr int MM   = NN * TT;       // 65536
constexpr int NH   = 8;
constexpr int CH   = 64;
constexpr int GRP  = 32;
constexpr int CPG  = CC / GRP;      // 16
constexpr int C3   = 3 * CC;        // 1536
constexpr float EPSF = 1e-6f;

// ---------------- scratch (static device globals) ----------------
__device__ float g_mean[BB * GRP * HWc];
__device__ float g_rstd[BB * GRP * HWc];
__device__ __half g_nh[(size_t)MM * CC];    // normed activations (fp16)
__device__ __half g_wqh[C3 * CC];           // qkv weights (fp16)
__device__ __half g_wph[CC * CC];           // proj weights (fp16)
__device__ __half g_qkv[(size_t)MM * C3];   // qkv output (fp16)
__device__ __half g_ah[(size_t)MM * CC];    // attention out (fp16)
__device__ __half g_pout[(size_t)MM * CC];  // proj out (fp16)

// ---------------- helpers ----------------
__device__ __forceinline__ uint32_t smem_u32(const void* p) {
    uint32_t a;
    asm("{ .reg .u64 t; cvta.to.shared.u64 t, %1; cvt.u32.u64 %0, t; }" : "=r"(a) : "l"(p));
    return a;
}
__device__ __forceinline__ void cpasync16(uint32_t dst, const void* src) {
    asm volatile("cp.async.cg.shared.global [%0], [%1], 16;" :: "r"(dst), "l"(src));
}
__device__ __forceinline__ void ldsm4(uint32_t* r, uint32_t a) {
    asm volatile("ldmatrix.sync.aligned.m8n8.x4.shared.b16 {%0,%1,%2,%3}, [%4];"
                 : "=r"(r[0]), "=r"(r[1]), "=r"(r[2]), "=r"(r[3]) : "r"(a));
}
__device__ __forceinline__ void mma16816(float* d, const uint32_t* a, uint32_t b0, uint32_t b1) {
    asm volatile(
        "mma.sync.aligned.m16n8k16.row.col.f32.f16.f16.f32 "
        "{%0,%1,%2,%3},{%4,%5,%6,%7},{%8,%9},{%0,%1,%2,%3};"
        : "+f"(d[0]), "+f"(d[1]), "+f"(d[2]), "+f"(d[3])
        : "r"(a[0]), "r"(a[1]), "r"(a[2]), "r"(a[3]), "r"(b0), "r"(b1));
}
__device__ __forceinline__ float dot4(float4 a, float4 b) {
    return a.x * b.x + a.y * b.y + a.z * b.z + a.w * b.w;
}
__device__ __forceinline__ void h4_to_f4(uint2 raw, float4& f) {
    __half2* hp = (__half2*)&raw;
    float2 a = __half22float2(hp[0]);
    float2 b = __half22float2(hp[1]);
    f.x = a.x; f.y = a.y; f.z = b.x; f.w = b.y;
}
__device__ __forceinline__ void h8_to_f8(uint4 raw, float* f) {
    __half2* hp = (__half2*)&raw;
    float2 a = __half22float2(hp[0]);
    float2 b = __half22float2(hp[1]);
    float2 c = __half22float2(hp[2]);
    float2 d = __half22float2(hp[3]);
    f[0] = a.x; f[1] = a.y; f[2] = b.x; f[3] = b.y;
    f[4] = c.x; f[5] = c.y; f[6] = d.x; f[7] = d.y;
}

// ---------------- 1) fused: group-norm stats (blocks 0..127) + weight convert ----------------
__global__ __launch_bounds__(1024) void gn_conv(const float* __restrict__ x,
                                                const float* __restrict__ wq,
                                                const float* __restrict__ wp) {
    int bx = blockIdx.x;
    if (bx < 128) {
        int b  = bx >> 5;
        int g  = bx & 31;
        int hw = threadIdx.x;
        float sum = 0.f, sq = 0.f;
        const float* base = x + ((size_t)b * CC + (size_t)g * CPG) * TT * HWc + hw;
        #pragma unroll 4
        for (int ct = 0; ct < CPG * TT; ct++) {
            float v = base[(size_t)ct * HWc];
            sum += v; sq += v * v;
        }
        float m   = sum * (1.0f / 256.0f);
        float var = sq  * (1.0f / 256.0f) - m * m;
        g_mean[(size_t)bx * HWc + hw] = m;
        g_rstd[(size_t)bx * HWc + hw] = rsqrtf(var + EPSF);
    } else {
        int i4 = (bx - 128) * 1024 + threadIdx.x;   // 0..262143 float4 chunks
        constexpr int NQ4 = C3 * CC / 4;            // 196608
        const float4* src;
        __half* h;
        int idx;
        if (i4 < NQ4) { src = (const float4*)wq; h = g_wqh; idx = i4; }
        else          { src = (const float4*)wp; h = g_wph; idx = i4 - NQ4; }
        float4 v = src[idx];
        __half hh[4] = {__float2half(v.x), __float2half(v.y),
                        __float2half(v.z), __float2half(v.w)};
        uint2 uh;
        uh.x = *(uint32_t*)&hh[0]; uh.y = *(uint32_t*)&hh[2];
        *(uint2*)(h + idx * 4) = uh;
    }
}

// ---------------- 2) normalize + transpose to fp16 [M,512] ----------------
__global__ __launch_bounds__(256) void norm_tr(const float* __restrict__ x,
                                               const float* __restrict__ gamma,
                                               const float* __restrict__ beta) {
    __shared__ float tile[32][33];
    int bx  = blockIdx.x;
    int hwt = bx & 31;
    int ct  = (bx >> 5) & 15;
    int t   = (bx >> 9) & 15;
    int b   = bx >> 13;
    int tid = threadIdx.x;
    {
        int hw_l = tid & 31;
        int c_l0 = tid >> 5;
        int hw   = hwt * 32 + hw_l;
        #pragma unroll
        for (int p = 0; p < 4; p++) {
            int c_l = c_l0 + p * 8;
            int c   = ct * 32 + c_l;
            int g   = c >> 4;
            float v = x[(((size_t)b * CC + c) * TT + t) * HWc + hw];
            size_t si = ((size_t)(b * GRP + g)) * HWc + hw;
            v = (v - g_mean[si]) * g_rstd[si] * gamma[c] + beta[c];
            tile[c_l][hw_l] = v;
        }
    }
    __syncthreads();
    {
        int c2    = (tid & 15) * 2;
        int hw_l0 = tid >> 4;
        #pragma unroll
        for (int p = 0; p < 2; p++) {
            int hw_l = hw_l0 + p * 16;
            int hw   = hwt * 32 + hw_l;
            size_t m = ((size_t)(b * HWc + hw)) * TT + t;
            float v0 = tile[c2][hw_l];
            float v1 = tile[c2 + 1][hw_l];
            size_t idx = m * CC + ct * 32 + c2;
            *(__half2*)(g_nh + idx) = __halves2half2(__float2half(v0), __float2half(v1));
        }
    }
}

// ---------------- HMMA GEMM: fragment-prefetch pipeline, 4-stage ring, fp16 out ----------------
constexpr int PITCH   = 80;
constexpr int TILE_B  = 128 * PITCH;   // 10240
constexpr int STAGE_B = 2 * TILE_B;    // 20480 (A, B)
constexpr int GEMM_SMEM = 4 * STAGE_B; // 81920

__global__ __launch_bounds__(256, 2) void hmma_gemm(const __half* __restrict__ A,
                                                    const __half* __restrict__ B,
                                                    const float* __restrict__ bias,
                                                    __half* __restrict__ Cout, int ldc) {
    extern __shared__ char smem[];
    uint32_t sb = smem_u32(smem);
    int tid = threadIdx.x;
    int n0 = blockIdx.x * 128;
    int m0 = blockIdx.y * 128;

    int r = tid >> 2;
    int c = tid & 3;
    const int4* pA = (const int4*)A + (size_t)(m0 + r) * 64 + c;
    const int4* pB = (const int4*)B + (size_t)(n0 + r) * 64 + c;
    uint32_t d0 = sb + r * PITCH + c * 16;
    constexpr int RSTEP = 64 * 64;
    constexpr int DSTEP = 64 * PITCH;

    auto issue = [&](int kk, int stage) {
        uint32_t dst = d0 + stage * STAGE_B;
        int ko = kk * 4;
        cpasync16(dst,                   pA + ko);
        cpasync16(dst + DSTEP,           pA + ko + RSTEP);
        cpasync16(dst + TILE_B,          pB + ko);
        cpasync16(dst + TILE_B + DSTEP,  pB + ko + RSTEP);
        asm volatile("cp.async.commit_group;");
    };

    float acc[4][4][4];
    #pragma unroll
    for (int a = 0; a < 4; a++)
        #pragma unroll
        for (int b = 0; b < 4; b++)
            #pragma unroll
            for (int cc = 0; cc < 4; cc++) acc[a][b][cc] = 0.f;

    int wid = tid >> 5, lane = tid & 31;
    int mw  = (wid >> 2) * 64;
    int nwv = (wid & 3) * 32;
    int lrow = lane & 15;
    int lk   = (lane >> 4) * 16;
    uint32_t adab = (mw + lrow) * PITCH + lk;
    uint32_t bdab = TILE_B + (nwv + lrow) * PITCH + lk;

    uint32_t amA[4][4], bmA[2][4];
    uint32_t amB[4][4], bmB[2][4];

    auto load_frags = [&](uint32_t am[4][4], uint32_t bm[2][4], uint32_t sa, int j) {
        #pragma unroll
        for (int mt = 0; mt < 4; mt++)
            ldsm4(am[mt], sa + adab + mt * (16 * PITCH) + j * 32);
        #pragma unroll
        for (int bt = 0; bt < 2; bt++)
            ldsm4(bm[bt], sa + bdab + bt * (16 * PITCH) + j * 32);
    };
    auto mma_all = [&](uint32_t am[4][4], uint32_t bm[2][4]) {
        #pragma unroll
        for (int mt = 0; mt < 4; mt++)
            #pragma unroll
            for (int nt = 0; nt < 4; nt++) {
                int bt = nt >> 1, s = nt & 1;
                mma16816(acc[mt][nt], am[mt], bm[bt][s], bm[bt][2 + s]);
            }
    };

    issue(0, 0);
    issue(1, 1);
    issue(2, 2);
    asm volatile("cp.async.wait_group 2;");
    __syncthreads();
    load_frags(amA, bmA, sb, 0);

    #pragma unroll 1
    for (int ks = 0; ks < 16; ks++) {
        if (ks < 14) asm volatile("cp.async.wait_group 1;");
        else         asm volatile("cp.async.wait_group 0;");
        __syncthreads();
        if (ks + 3 < 16) issue(ks + 3, (ks + 3) & 3);

        uint32_t sa  = sb + (ks & 3) * STAGE_B;
        uint32_t san = sb + ((ks + 1) & 3) * STAGE_B;

        load_frags(amB, bmB, sa, 1);
        mma_all(amA, bmA);
        if (ks < 15) load_frags(amA, bmA, san, 0);
        mma_all(amB, bmB);
    }

    int row_in = lane >> 2;
    int colq   = (lane & 3) * 2;
    #pragma unroll
    for (int mt = 0; mt < 4; mt++) {
        int gr = m0 + mw + mt * 16 + row_in;
        #pragma unroll
        for (int nt = 0; nt < 4; nt++) {
            int gc = n0 + nwv + nt * 8 + colq;
            float b0 = bias[gc], b1 = bias[gc + 1];
            *(__half2*)(Cout + (size_t)gr * ldc + gc) =
                __halves2half2(__float2half(acc[mt][nt][0] + b0),
                               __float2half(acc[mt][nt][1] + b1));
            *(__half2*)(Cout + (size_t)(gr + 8) * ldc + gc) =
                __halves2half2(__float2half(acc[mt][nt][2] + b0),
                               __float2half(acc[mt][nt][3] + b1));
        }
    }
}

// ---------------- 4) attention: one block per n, fp16 q/k/v smem, 2 CTAs/SM ----------------
constexpr int QPH = 520;                       // halves per row pitch
constexpr int RP  = 68;                        // floats per rp row
constexpr int OFFB_Q  = 0;
constexpr int OFFB_K  = OFFB_Q + 16 * QPH * 2;     // 16640
constexpr int OFFB_V  = OFFB_K + 16 * QPH * 2;     // 33280
constexpr int OFFB_RK = OFFB_V + 16 * QPH * 2;     // 49920
constexpr int OFFB_RV = OFFB_RK + 31 * RP * 4;     // 58352
constexpr int OFFB_WS = OFFB_RV + 31 * RP * 4;     // 66784
constexpr int ATTN_SMEM = OFFB_WS + 8 * 16 * 17 * 4;  // 75488

__global__ __launch_bounds__(256, 2) void attn(const float* __restrict__ rp_k,
                                               const float* __restrict__ rp_v) {
    extern __shared__ char smc[];
    __half* qh = (__half*)(smc + OFFB_Q);
    __half* kh = (__half*)(smc + OFFB_K);
    __half* vh = (__half*)(smc + OFFB_V);
    float*  rk = (float*)(smc + OFFB_RK);
    float*  rv = (float*)(smc + OFFB_RV);
    float*  ws = (float*)(smc + OFFB_WS);

    int n   = blockIdx.x;
    int tid = threadIdx.x;

    // ---- load: pure bit-copy of fp16 qkv ----
    const uint4* gq = reinterpret_cast<const uint4*>(g_qkv);
    #pragma unroll
    for (int it = 0; it < 12; it++) {
        int idx = it * 256 + tid;          // 0..3071
        int t   = idx / 192;
        int rem = idx - t * 192;
        int which = rem >> 6;              // 0=q 1=k 2=v
        int c8    = rem & 63;
        uint4 raw = gq[(size_t)(n * TT + t) * 192 + rem];
        __half* dst = (which == 0 ? qh : which == 1 ? kh : vh) + t * QPH + c8 * 8;
        *(uint4*)dst = raw;
    }
    const float4* grk = reinterpret_cast<const float4*>(rp_k);
    const float4* grv = reinterpret_cast<const float4*>(rp_v);
    for (int idx = tid; idx < 992; idx += 256) {
        int half = idx >= 496;
        int r = idx - half * 496;
        int row = r >> 4, c4 = r & 15;
        float4 val = (half ? grv : grk)[(49 + row) * 16 + c4];
        *(float4*)((half ? rv : rk) + row * RP + c4 * 4) = val;
    }
    __syncthreads();

    // ---- score phase ----
    {
        int h = tid >> 5;
        int r5 = tid & 31;
        int tile = r5 & 15;
        int chalf = r5 >> 4;
        int ti = (tile >> 2) << 2;
        int tj = (tile & 3) << 2;
        int cb = h * 64 + chalf * 32;               // halves
        const float* rkb = rk + (ti - tj + 12) * RP + chalf * 32;

        float accC[4][4], accR[4][4];
        #pragma unroll
        for (int a = 0; a < 4; a++)
            #pragma unroll
            for (int b = 0; b < 4; b++) { accC[a][b] = 0.f; accR[a][b] = 0.f; }

        #pragma unroll
        for (int c4 = 0; c4 < 8; c4++) {
            int ch = cb + c4 * 4;
            float4 qi[4], kj[4], qj[4], rr[7];
            #pragma unroll
            for (int a = 0; a < 4; a++)
                h4_to_f4(*(uint2*)(qh + (ti + a) * QPH + ch), qi[a]);
            #pragma unroll
            for (int b = 0; b < 4; b++) {
                h4_to_f4(*(uint2*)(kh + (tj + b) * QPH + ch), kj[b]);
                h4_to_f4(*(uint2*)(qh + (tj + b) * QPH + ch), qj[b]);
            }
            #pragma unroll
            for (int e = 0; e < 7; e++) rr[e] = *(const float4*)(rkb + e * RP + c4 * 4);
            #pragma unroll
            for (int a = 0; a < 4; a++)
                #pragma unroll
                for (int b = 0; b < 4; b++) {
                    accC[a][b] += dot4(qi[a], kj[b]);
                    accR[a][b] += dot4(qj[b], rr[a - b + 3]);
                }
        }
        #pragma unroll
        for (int a = 0; a < 4; a++)
            #pragma unroll
            for (int b = 0; b < 4; b++) {
                float s = accC[a][b] * 0.125f + accR[a][b] * 0.35355339059327373f;
                s += __shfl_xor_sync(0xFFFFFFFFu, s, 16);
                if (chalf == 0) ws[h * 272 + (ti + a) * 17 + tj + b] = s;
            }
    }
    __syncthreads();

    // ---- softmax ----
    if (tid < 128) {
        int h = tid >> 4, i = tid & 15;
        float* wp = ws + h * 272 + i * 17;
        float mx = -1e30f;
        #pragma unroll
        for (int j = 0; j < 16; j++) mx = fmaxf(mx, wp[j]);
        float e[16]; float sum = 0.f;
        #pragma unroll
        for (int j = 0; j < 16; j++) { e[j] = __expf(wp[j] - mx); sum += e[j]; }
        float inv = 1.f / sum;
        #pragma unroll
        for (int j = 0; j < 16; j++) wp[j] = e[j] * inv;
    }
    __syncthreads();

    // ---- output phase ----
    {
        int h = tid >> 5;
        int r5 = tid & 31;
        int tgrp = r5 >> 3;
        int cq = r5 & 7;
        int t0 = tgrp * 4;
        int c = h * 64 + cq * 8;
        const float* wsb = ws + h * 272;

        float acc[4][8];
        #pragma unroll
        for (int t = 0; t < 4; t++)
            #pragma unroll
            for (int j = 0; j < 8; j++) acc[t][j] = 0.f;

        #pragma unroll
        for (int s = 0; s < 16; s++) {
            uint4 raw = *(uint4*)(vh + s * QPH + c);
            float vf[8];
            h8_to_f8(raw, vf);
            #pragma unroll
            for (int t = 0; t < 4; t++) {
                float wv = wsb[(t0 + t) * 17 + s];
                #pragma unroll
                for (int j = 0; j < 8; j++) acc[t][j] += wv * vf[j];
            }
        }
        #pragma unroll
        for (int d = 0; d < 31; d++) {
            float4 r0 = *(const float4*)(rv + d * RP + cq * 8);
            float4 r1 = *(const float4*)(rv + d * RP + cq * 8 + 4);
            #pragma unroll
            for (int t = 0; t < 4; t++) {
                int s = d + t0 + t - 15;
                if (s >= 0 && s < 16) {
                    float wv = wsb[(t0 + t) * 17 + s];
                    acc[t][0] += wv * r0.x; acc[t][1] += wv * r0.y;
                    acc[t][2] += wv * r0.z; acc[t][3] += wv * r0.w;
                    acc[t][4] += wv * r1.x; acc[t][5] += wv * r1.y;
                    acc[t][6] += wv * r1.z; acc[t][7] += wv * r1.w;
                }
            }
        }
        #pragma unroll
        for (int t = 0; t < 4; t++) {
            size_t idx = ((size_t)(n * TT + t0 + t)) * CC + c;
            uint4 uh;
            __half hh[8];
            #pragma unroll
            for (int j = 0; j < 8; j++) hh[j] = __float2half(acc[t][j]);
            uh.x = *(uint32_t*)&hh[0]; uh.y = *(uint32_t*)&hh[2];
            uh.z = *(uint32_t*)&hh[4]; uh.w = *(uint32_t*)&hh[6];
            *(uint4*)(g_ah + idx) = uh;
        }
    }
}

// ---------------- 6) transpose back + residual (fp16 pout) ----------------
__global__ __launch_bounds__(256) void resid_tr(const float* __restrict__ x,
                                                float* __restrict__ out) {
    __shared__ float tile[32][33];
    int bx  = blockIdx.x;
    int hwt = bx & 31;
    int ct  = (bx >> 5) & 15;
    int t   = (bx >> 9) & 15;
    int b   = bx >> 13;
    int tid = threadIdx.x;
    {
        int c2    = (tid & 15) * 2;
        int hw_l0 = tid >> 4;
        #pragma unroll
        for (int p = 0; p < 2; p++) {
            int hw_l = hw_l0 + p * 16;
            int hw   = hwt * 32 + hw_l;
            size_t m = ((size_t)(b * HWc + hw)) * TT + t;
            __half2 hv = *(const __half2*)(g_pout + m * CC + ct * 32 + c2);
            float2 f = __half22float2(hv);
            tile[hw_l][c2]     = f.x;
            tile[hw_l][c2 + 1] = f.y;
        }
    }
    __syncthreads();
    {
        int hw_l = tid & 31;
        int c_l0 = tid >> 5;
        int hw   = hwt * 32 + hw_l;
        #pragma unroll
        for (int p = 0; p < 4; p++) {
            int c_l = c_l0 + p * 8;
            int c   = ct * 32 + c_l;
            size_t idx = (((size_t)b * CC + c) * TT + t) * HWc + hw;
            out[idx] = x[idx] + tile[hw_l][c_l];
        }
    }
}

// ---------------- host launch ----------------
extern "C" void kernel_launch(void* const* d_in, const int* in_sizes, int n_in,
                              void* d_out, int out_size) {
    const float* x      = (const float*)d_in[0];
    const float* gamma  = (const float*)d_in[1];
    const float* beta   = (const float*)d_in[2];
    const float* w_qkv  = (const float*)d_in[3];
    const float* b_qkv  = (const float*)d_in[4];
    const float* rp_k   = (const float*)d_in[5];
    const float* rp_v   = (const float*)d_in[6];
    const float* w_proj = (const float*)d_in[7];
    const float* b_proj = (const float*)d_in[8];
    float* out = (float*)d_out;

    cudaFuncSetAttribute(hmma_gemm, cudaFuncAttributeMaxDynamicSharedMemorySize, GEMM_SMEM);
    cudaFuncSetAttribute(attn, cudaFuncAttributeMaxDynamicSharedMemorySize, ATTN_SMEM);

    __half *wqh, *wph, *nh, *ah, *qkv, *pout;
    cudaGetSymbolAddress((void**)&wqh, g_wqh);
    cudaGetSymbolAddress((void**)&wph, g_wph);
    cudaGetSymbolAddress((void**)&nh, g_nh);
    cudaGetSymbolAddress((void**)&ah, g_ah);
    cudaGetSymbolAddress((void**)&qkv, g_qkv);
    cudaGetSymbolAddress((void**)&pout, g_pout);

    // launch order: attn is #4 (ncu profile target this round)
    gn_conv<<<384, 1024>>>(x, w_qkv, w_proj);
    norm_tr<<<BB * TT * (CC / 32) * (HWc / 32), 256>>>(x, gamma, beta);
    hmma_gemm<<<dim3(C3 / 128, MM / 128), 256, GEMM_SMEM>>>(nh, wqh, b_qkv, qkv, C3);
    attn<<<NN, 256, ATTN_SMEM>>>(rp_k, rp_v);
    hmma_gemm<<<dim3(CC / 128, MM / 128), 256, GEMM_SMEM>>>(ah, wph, b_proj, pout, CC);
    resid_tr<<<BB * TT * (CC / 32) * (HWc / 32), 256>>>(x, out);
}

// round 12
// speedup vs baseline: 1.2963x; 1.0548x over previous
#include <cuda_runtime.h>
#include <cuda_fp16.h>
#include <stdint.h>
#include <math.h>

// ---------------- problem constants ----------------
constexpr int BB   = 4;
constexpr int CC   = 512;
constexpr int TT   = 16;
constexpr int HWc  = 1024;
constexpr int NN   = BB * HWc;      // 4096
constexpr int MM   = NN * TT;       // 65536
constexpr int NH   = 8;
constexpr int CH   = 64;
constexpr int GRP  = 32;
constexpr int CPG  = CC / GRP;      // 16
constexpr int C3   = 3 * CC;        // 1536
constexpr float EPSF = 1e-6f;

// ---------------- scratch (static device globals) ----------------
__device__ float g_mean[BB * GRP * HWc];
__device__ float g_rstd[BB * GRP * HWc];
__device__ __half g_nh[(size_t)MM * CC];    // normed activations (fp16)
__device__ __half g_wqh[C3 * CC];           // qkv weights (fp16)
__device__ __half g_wph[CC * CC];           // proj weights (fp16)
__device__ __half g_qkv[(size_t)MM * C3];   // qkv output (fp16)
__device__ __half g_ah[(size_t)MM * CC];    // attention out (fp16)
__device__ __half g_pout[(size_t)MM * CC];  // proj out (fp16)

// ---------------- helpers ----------------
__device__ __forceinline__ uint32_t smem_u32(const void* p) {
    uint32_t a;
    asm("{ .reg .u64 t; cvta.to.shared.u64 t, %1; cvt.u32.u64 %0, t; }" : "=r"(a) : "l"(p));
    return a;
}
__device__ __forceinline__ void cpasync16(uint32_t dst, const void* src) {
    asm volatile("cp.async.cg.shared.global [%0], [%1], 16;" :: "r"(dst), "l"(src));
}
__device__ __forceinline__ void ldsm4(uint32_t* r, uint32_t a) {
    asm volatile("ldmatrix.sync.aligned.m8n8.x4.shared.b16 {%0,%1,%2,%3}, [%4];"
                 : "=r"(r[0]), "=r"(r[1]), "=r"(r[2]), "=r"(r[3]) : "r"(a));
}
__device__ __forceinline__ void mma16816(float* d, const uint32_t* a, uint32_t b0, uint32_t b1) {
    asm volatile(
        "mma.sync.aligned.m16n8k16.row.col.f32.f16.f16.f32 "
        "{%0,%1,%2,%3},{%4,%5,%6,%7},{%8,%9},{%0,%1,%2,%3};"
        : "+f"(d[0]), "+f"(d[1]), "+f"(d[2]), "+f"(d[3])
        : "r"(a[0]), "r"(a[1]), "r"(a[2]), "r"(a[3]), "r"(b0), "r"(b1));
}
__device__ __forceinline__ void h8_to_f8(uint4 raw, float* f) {
    __half2* hp = (__half2*)&raw;
    float2 a = __half22float2(hp[0]);
    float2 b = __half22float2(hp[1]);
    float2 c = __half22float2(hp[2]);
    float2 d = __half22float2(hp[3]);
    f[0] = a.x; f[1] = a.y; f[2] = b.x; f[3] = b.y;
    f[4] = c.x; f[5] = c.y; f[6] = d.x; f[7] = d.y;
}
__device__ __forceinline__ void h8_to_f8_scaled(uint4 raw, float* f, float s) {
    h8_to_f8(raw, f);
    #pragma unroll
    for (int i = 0; i < 8; i++) f[i] *= s;
}

// ---------------- 1) fused: group-norm stats (blocks 0..127) + weight convert ----------------
__global__ __launch_bounds__(1024) void gn_conv(const float* __restrict__ x,
                                                const float* __restrict__ wq,
                                                const float* __restrict__ wp) {
    int bx = blockIdx.x;
    if (bx < 128) {
        int b  = bx >> 5;
        int g  = bx & 31;
        int hw = threadIdx.x;
        float sum = 0.f, sq = 0.f;
        const float* base = x + ((size_t)b * CC + (size_t)g * CPG) * TT * HWc + hw;
        #pragma unroll 4
        for (int ct = 0; ct < CPG * TT; ct++) {
            float v = base[(size_t)ct * HWc];
            sum += v; sq += v * v;
        }
        float m   = sum * (1.0f / 256.0f);
        float var = sq  * (1.0f / 256.0f) - m * m;
        g_mean[(size_t)bx * HWc + hw] = m;
        g_rstd[(size_t)bx * HWc + hw] = rsqrtf(var + EPSF);
    } else {
        int i4 = (bx - 128) * 1024 + threadIdx.x;
        constexpr int NQ4 = C3 * CC / 4;
        const float4* src;
        __half* h;
        int idx;
        if (i4 < NQ4) { src = (const float4*)wq; h = g_wqh; idx = i4; }
        else          { src = (const float4*)wp; h = g_wph; idx = i4 - NQ4; }
        float4 v = src[idx];
        __half hh[4] = {__float2half(v.x), __float2half(v.y),
                        __float2half(v.z), __float2half(v.w)};
        uint2 uh;
        uh.x = *(uint32_t*)&hh[0]; uh.y = *(uint32_t*)&hh[2];
        *(uint2*)(h + idx * 4) = uh;
    }
}

// ---------------- 2) normalize + transpose to fp16 [M,512] ----------------
__global__ __launch_bounds__(256) void norm_tr(const float* __restrict__ x,
                                               const float* __restrict__ gamma,
                                               const float* __restrict__ beta) {
    __shared__ float tile[32][33];
    int bx  = blockIdx.x;
    int hwt = bx & 31;
    int ct  = (bx >> 5) & 15;
    int t   = (bx >> 9) & 15;
    int b   = bx >> 13;
    int tid = threadIdx.x;
    {
        int hw_l = tid & 31;
        int c_l0 = tid >> 5;
        int hw   = hwt * 32 + hw_l;
        #pragma unroll
        for (int p = 0; p < 4; p++) {
            int c_l = c_l0 + p * 8;
            int c   = ct * 32 + c_l;
            int g   = c >> 4;
            float v = x[(((size_t)b * CC + c) * TT + t) * HWc + hw];
            size_t si = ((size_t)(b * GRP + g)) * HWc + hw;
            v = (v - g_mean[si]) * g_rstd[si] * gamma[c] + beta[c];
            tile[c_l][hw_l] = v;
        }
    }
    __syncthreads();
    {
        int c2    = (tid & 15) * 2;
        int hw_l0 = tid >> 4;
        #pragma unroll
        for (int p = 0; p < 2; p++) {
            int hw_l = hw_l0 + p * 16;
            int hw   = hwt * 32 + hw_l;
            size_t m = ((size_t)(b * HWc + hw)) * TT + t;
            float v0 = tile[c2][hw_l];
            float v1 = tile[c2 + 1][hw_l];
            size_t idx = m * CC + ct * 32 + c2;
            *(__half2*)(g_nh + idx) = __halves2half2(__float2half(v0), __float2half(v1));
        }
    }
}

// ---------------- HMMA GEMM: fragment-prefetch pipeline, 4-stage ring, fp16 out ----------------
constexpr int PITCH   = 80;
constexpr int TILE_B  = 128 * PITCH;   // 10240
constexpr int STAGE_B = 2 * TILE_B;    // 20480 (A, B)
constexpr int GEMM_SMEM = 4 * STAGE_B; // 81920

__global__ __launch_bounds__(256, 2) void hmma_gemm(const __half* __restrict__ A,
                                                    const __half* __restrict__ B,
                                                    const float* __restrict__ bias,
                                                    __half* __restrict__ Cout, int ldc) {
    extern __shared__ char smem[];
    uint32_t sb = smem_u32(smem);
    int tid = threadIdx.x;
    int n0 = blockIdx.x * 128;
    int m0 = blockIdx.y * 128;

    int r = tid >> 2;
    int c = tid & 3;
    const int4* pA = (const int4*)A + (size_t)(m0 + r) * 64 + c;
    const int4* pB = (const int4*)B + (size_t)(n0 + r) * 64 + c;
    uint32_t d0 = sb + r * PITCH + c * 16;
    constexpr int RSTEP = 64 * 64;
    constexpr int DSTEP = 64 * PITCH;

    auto issue = [&](int kk, int stage) {
        uint32_t dst = d0 + stage * STAGE_B;
        int ko = kk * 4;
        cpasync16(dst,                   pA + ko);
        cpasync16(dst + DSTEP,           pA + ko + RSTEP);
        cpasync16(dst + TILE_B,          pB + ko);
        cpasync16(dst + TILE_B + DSTEP,  pB + ko + RSTEP);
        asm volatile("cp.async.commit_group;");
    };

    float acc[4][4][4];
    #pragma unroll
    for (int a = 0; a < 4; a++)
        #pragma unroll
        for (int b = 0; b < 4; b++)
            #pragma unroll
            for (int cc = 0; cc < 4; cc++) acc[a][b][cc] = 0.f;

    int wid = tid >> 5, lane = tid & 31;
    int mw  = (wid >> 2) * 64;
    int nwv = (wid & 3) * 32;
    int lrow = lane & 15;
    int lk   = (lane >> 4) * 16;
    uint32_t adab = (mw + lrow) * PITCH + lk;
    uint32_t bdab = TILE_B + (nwv + lrow) * PITCH + lk;

    uint32_t amA[4][4], bmA[2][4];
    uint32_t amB[4][4], bmB[2][4];

    auto load_frags = [&](uint32_t am[4][4], uint32_t bm[2][4], uint32_t sa, int j) {
        #pragma unroll
        for (int mt = 0; mt < 4; mt++)
            ldsm4(am[mt], sa + adab + mt * (16 * PITCH) + j * 32);
        #pragma unroll
        for (int bt = 0; bt < 2; bt++)
            ldsm4(bm[bt], sa + bdab + bt * (16 * PITCH) + j * 32);
    };
    auto mma_all = [&](uint32_t am[4][4], uint32_t bm[2][4]) {
        #pragma unroll
        for (int mt = 0; mt < 4; mt++)
            #pragma unroll
            for (int nt = 0; nt < 4; nt++) {
                int bt = nt >> 1, s = nt & 1;
                mma16816(acc[mt][nt], am[mt], bm[bt][s], bm[bt][2 + s]);
            }
    };

    issue(0, 0);
    issue(1, 1);
    issue(2, 2);
    asm volatile("cp.async.wait_group 2;");
    __syncthreads();
    load_frags(amA, bmA, sb, 0);

    #pragma unroll 1
    for (int ks = 0; ks < 16; ks++) {
        if (ks < 14) asm volatile("cp.async.wait_group 1;");
        else         asm volatile("cp.async.wait_group 0;");
        __syncthreads();
        if (ks + 3 < 16) issue(ks + 3, (ks + 3) & 3);

        uint32_t sa  = sb + (ks & 3) * STAGE_B;
        uint32_t san = sb + ((ks + 1) & 3) * STAGE_B;

        load_frags(amB, bmB, sa, 1);
        mma_all(amA, bmA);
        if (ks < 15) load_frags(amA, bmA, san, 0);
        mma_all(amB, bmB);
    }

    int row_in = lane >> 2;
    int colq   = (lane & 3) * 2;
    #pragma unroll
    for (int mt = 0; mt < 4; mt++) {
        int gr = m0 + mw + mt * 16 + row_in;
        #pragma unroll
        for (int nt = 0; nt < 4; nt++) {
            int gc = n0 + nwv + nt * 8 + colq;
            float b0 = bias[gc], b1 = bias[gc + 1];
            *(__half2*)(Cout + (size_t)gr * ldc + gc) =
                __halves2half2(__float2half(acc[mt][nt][0] + b0),
                               __float2half(acc[mt][nt][1] + b1));
            *(__half2*)(Cout + (size_t)(gr + 8) * ldc + gc) =
                __halves2half2(__float2half(acc[mt][nt][2] + b0),
                               __float2half(acc[mt][nt][3] + b1));
        }
    }
}

// ---------------- 4) attention: fp16 smem everywhere, wide LDS ----------------
constexpr int QPH = 520;                       // halves pitch for q/k/v rows
constexpr int RPH = 72;                        // halves pitch for rp rows
constexpr int OFFB_Q  = 0;
constexpr int OFFB_K  = OFFB_Q + 16 * QPH * 2;     // 16640
constexpr int OFFB_V  = OFFB_K + 16 * QPH * 2;     // 33280
constexpr int OFFB_RK = OFFB_V + 16 * QPH * 2;     // 49920
constexpr int OFFB_RV = OFFB_RK + 31 * RPH * 2;    // 54384
constexpr int OFFB_WS = OFFB_RV + 31 * RPH * 2;    // 58848
constexpr int ATTN_SMEM = OFFB_WS + 8 * 16 * 17 * 4;  // 67552

__global__ __launch_bounds__(256, 2) void attn(const float* __restrict__ rp_k,
                                               const float* __restrict__ rp_v) {
    extern __shared__ char smc[];
    __half* qh  = (__half*)(smc + OFFB_Q);
    __half* kh  = (__half*)(smc + OFFB_K);
    __half* vh  = (__half*)(smc + OFFB_V);
    __half* rkh = (__half*)(smc + OFFB_RK);
    __half* rvh = (__half*)(smc + OFFB_RV);
    float*  ws  = (float*)(smc + OFFB_WS);

    int n   = blockIdx.x;
    int tid = threadIdx.x;

    // ---- load: bit-copy fp16 qkv ----
    const uint4* gq = reinterpret_cast<const uint4*>(g_qkv);
    #pragma unroll
    for (int it = 0; it < 12; it++) {
        int idx = it * 256 + tid;
        int t   = idx / 192;
        int rem = idx - t * 192;
        int which = rem >> 6;
        int c8    = rem & 63;
        uint4 raw = gq[(size_t)(n * TT + t) * 192 + rem];
        __half* dst = (which == 0 ? qh : which == 1 ? kh : vh) + t * QPH + c8 * 8;
        *(uint4*)dst = raw;
    }
    // ---- load rp, convert to fp16 ----
    const float4* grk = reinterpret_cast<const float4*>(rp_k);
    const float4* grv = reinterpret_cast<const float4*>(rp_v);
    for (int idx = tid; idx < 992; idx += 256) {
        int hsel = idx >= 496;
        int r = idx - hsel * 496;
        int row = r >> 4, c4 = r & 15;
        float4 val = (hsel ? grv : grk)[(49 + row) * 16 + c4];
        __half h0 = __float2half(val.x), h1 = __float2half(val.y);
        __half h2 = __float2half(val.z), h3 = __float2half(val.w);
        uint2 u;
        u.x = ((uint32_t)*(uint16_t*)&h1 << 16) | *(uint16_t*)&h0;
        u.y = ((uint32_t)*(uint16_t*)&h3 << 16) | *(uint16_t*)&h2;
        *(uint2*)((hsel ? rvh : rkh) + row * RPH + c4 * 4) = u;
    }
    __syncthreads();

    // ---- score phase: 8-half chunks, scales folded into converted q ----
    {
        int h = tid >> 5;
        int r5 = tid & 31;
        int tile = r5 & 15;
        int chalf = r5 >> 4;
        int ti = (tile >> 2) << 2;
        int tj = (tile & 3) << 2;
        int cb = h * 64 + chalf * 32;
        int dbase = ti - tj + 12;
        const float SC = 0.125f;               // content scale (64^-0.5)
        const float SR = 0.35355339059327373f; // rel scale (64^-0.25)

        float acc[4][4];
        #pragma unroll
        for (int a = 0; a < 4; a++)
            #pragma unroll
            for (int b = 0; b < 4; b++) acc[a][b] = 0.f;

        #pragma unroll
        for (int c8 = 0; c8 < 4; c8++) {
            int ch = cb + c8 * 8;
            // content: q_i . k_j (scale folded into q)
            float kf[4][8];
            #pragma unroll
            for (int b = 0; b < 4; b++)
                h8_to_f8(*(uint4*)(kh + (tj + b) * QPH + ch), kf[b]);
            #pragma unroll
            for (int a = 0; a < 4; a++) {
                float qf[8];
                h8_to_f8_scaled(*(uint4*)(qh + (ti + a) * QPH + ch), qf, SC);
                #pragma unroll
                for (int b = 0; b < 4; b++) {
                    float s = 0.f;
                    #pragma unroll
                    for (int e = 0; e < 8; e++) s += qf[e] * kf[b][e];
                    acc[a][b] += s;
                }
            }
            // rel: q_j . rp_k[i-j+64] (scale folded into q)
            float qjf[4][8];
            #pragma unroll
            for (int b = 0; b < 4; b++)
                h8_to_f8_scaled(*(uint4*)(qh + (tj + b) * QPH + ch), qjf[b], SR);
            #pragma unroll
            for (int d = 0; d < 7; d++) {
                float rf[8];
                h8_to_f8(*(uint4*)(rkh + (dbase + d) * RPH + chalf * 32 + c8 * 8), rf);
                #pragma unroll
                for (int b = 0; b < 4; b++) {
                    int a = b + d - 3;
                    if (a >= 0 && a < 4) {
                        float s = 0.f;
                        #pragma unroll
                        for (int e = 0; e < 8; e++) s += qjf[b][e] * rf[e];
                        acc[a][b] += s;
                    }
                }
            }
        }
        #pragma unroll
        for (int a = 0; a < 4; a++)
            #pragma unroll
            for (int b = 0; b < 4; b++) {
                float s = acc[a][b];
                s += __shfl_xor_sync(0xFFFFFFFFu, s, 16);
                if (chalf == 0) ws[h * 272 + (ti + a) * 17 + tj + b] = s;
            }
    }
    __syncthreads();

    // ---- softmax ----
    if (tid < 128) {
        int h = tid >> 4, i = tid & 15;
        float* wp = ws + h * 272 + i * 17;
        float mx = -1e30f;
        #pragma unroll
        for (int j = 0; j < 16; j++) mx = fmaxf(mx, wp[j]);
        float e[16]; float sum = 0.f;
        #pragma unroll
        for (int j = 0; j < 16; j++) { e[j] = __expf(wp[j] - mx); sum += e[j]; }
        float inv = 1.f / sum;
        #pragma unroll
        for (int j = 0; j < 16; j++) wp[j] = e[j] * inv;
    }
    __syncthreads();

    // ---- output phase ----
    {
        int h = tid >> 5;
        int r5 = tid & 31;
        int tgrp = r5 >> 3;
        int cq = r5 & 7;
        int t0 = tgrp * 4;
        int c = h * 64 + cq * 8;
        const float* wsb = ws + h * 272;

        float acc[4][8];
        #pragma unroll
        for (int t = 0; t < 4; t++)
            #pragma unroll
            for (int j = 0; j < 8; j++) acc[t][j] = 0.f;

        #pragma unroll
        for (int s = 0; s < 16; s++) {
            float vf[8];
            h8_to_f8(*(uint4*)(vh + s * QPH + c), vf);
            #pragma unroll
            for (int t = 0; t < 4; t++) {
                float wv = wsb[(t0 + t) * 17 + s];
                #pragma unroll
                for (int j = 0; j < 8; j++) acc[t][j] += wv * vf[j];
            }
        }
        #pragma unroll
        for (int d = 0; d < 31; d++) {
            float rf[8];
            h8_to_f8(*(uint4*)(rvh + d * RPH + cq * 8), rf);
            #pragma unroll
            for (int t = 0; t < 4; t++) {
                int s = d + t0 + t - 15;
                if (s >= 0 && s < 16) {
                    float wv = wsb[(t0 + t) * 17 + s];
                    #pragma unroll
                    for (int j = 0; j < 8; j++) acc[t][j] += wv * rf[j];
                }
            }
        }
        #pragma unroll
        for (int t = 0; t < 4; t++) {
            size_t idx = ((size_t)(n * TT + t0 + t)) * CC + c;
            uint4 uh;
            __half hh[8];
            #pragma unroll
            for (int j = 0; j < 8; j++) hh[j] = __float2half(acc[t][j]);
            uh.x = *(uint32_t*)&hh[0]; uh.y = *(uint32_t*)&hh[2];
            uh.z = *(uint32_t*)&hh[4]; uh.w = *(uint32_t*)&hh[6];
            *(uint4*)(g_ah + idx) = uh;
        }
    }
}

// ---------------- 6) transpose back + residual (fp16 pout) ----------------
__global__ __launch_bounds__(256) void resid_tr(const float* __restrict__ x,
                                                float* __restrict__ out) {
    __shared__ float tile[32][33];
    int bx  = blockIdx.x;
    int hwt = bx & 31;
    int ct  = (bx >> 5) & 15;
    int t   = (bx >> 9) & 15;
    int b   = bx >> 13;
    int tid = threadIdx.x;
    {
        int c2    = (tid & 15) * 2;
        int hw_l0 = tid >> 4;
        #pragma unroll
        for (int p = 0; p < 2; p++) {
            int hw_l = hw_l0 + p * 16;
            int hw   = hwt * 32 + hw_l;
            size_t m = ((size_t)(b * HWc + hw)) * TT + t;
            __half2 hv = *(const __half2*)(g_pout + m * CC + ct * 32 + c2);
            float2 f = __half22float2(hv);
            tile[hw_l][c2]     = f.x;
            tile[hw_l][c2 + 1] = f.y;
        }
    }
    __syncthreads();
    {
        int hw_l = tid & 31;
        int c_l0 = tid >> 5;
        int hw   = hwt * 32 + hw_l;
        #pragma unroll
        for (int p = 0; p < 4; p++) {
            int c_l = c_l0 + p * 8;
            int c   = ct * 32 + c_l;
            size_t idx = (((size_t)b * CC + c) * TT + t) * HWc + hw;
            out[idx] = x[idx] + tile[hw_l][c_l];
        }
    }
}

// ---------------- host launch ----------------
extern "C" void kernel_launch(void* const* d_in, const int* in_sizes, int n_in,
                              void* d_out, int out_size) {
    const float* x      = (const float*)d_in[0];
    const float* gamma  = (const float*)d_in[1];
    const float* beta   = (const float*)d_in[2];
    const float* w_qkv  = (const float*)d_in[3];
    const float* b_qkv  = (const float*)d_in[4];
    const float* rp_k   = (const float*)d_in[5];
    const float* rp_v   = (const float*)d_in[6];
    const float* w_proj = (const float*)d_in[7];
    const float* b_proj = (const float*)d_in[8];
    float* out = (float*)d_out;

    cudaFuncSetAttribute(hmma_gemm, cudaFuncAttributeMaxDynamicSharedMemorySize, GEMM_SMEM);
    cudaFuncSetAttribute(attn, cudaFuncAttributeMaxDynamicSharedMemorySize, ATTN_SMEM);

    __half *wqh, *wph, *nh, *ah, *qkv, *pout;
    cudaGetSymbolAddress((void**)&wqh, g_wqh);
    cudaGetSymbolAddress((void**)&wph, g_wph);
    cudaGetSymbolAddress((void**)&nh, g_nh);
    cudaGetSymbolAddress((void**)&ah, g_ah);
    cudaGetSymbolAddress((void**)&qkv, g_qkv);
    cudaGetSymbolAddress((void**)&pout, g_pout);

    // launch order: attn stays #4 (ncu target: verify the wavefront cut)
    gn_conv<<<384, 1024>>>(x, w_qkv, w_proj);
    norm_tr<<<BB * TT * (CC / 32) * (HWc / 32), 256>>>(x, gamma, beta);
    hmma_gemm<<<dim3(C3 / 128, MM / 128), 256, GEMM_SMEM>>>(nh, wqh, b_qkv, qkv, C3);
    attn<<<NN, 256, ATTN_SMEM>>>(rp_k, rp_v);
    hmma_gemm<<<dim3(CC / 128, MM / 128), 256, GEMM_SMEM>>>(ah, wph, b_proj, pout, CC);
    resid_tr<<<BB * TT * (CC / 32) * (HWc / 32), 256>>>(x, out);
}

// round 13
// speedup vs baseline: 1.4873x; 1.1473x over previous
#include <cuda_runtime.h>
#include <cuda_fp16.h>
#include <stdint.h>
#include <math.h>

// ---------------- problem constants ----------------
constexpr int BB   = 4;
constexpr int CC   = 512;
constexpr int TT   = 16;
constexpr int HWc  = 1024;
constexpr int NN   = BB * HWc;      // 4096
constexpr int MM   = NN * TT;       // 65536
constexpr int NH   = 8;
constexpr int CH   = 64;
constexpr int GRP  = 32;
constexpr int CPG  = CC / GRP;      // 16
constexpr int C3   = 3 * CC;        // 1536
constexpr float EPSF = 1e-6f;

// ---------------- scratch (static device globals) ----------------
__device__ float g_mean[BB * GRP * HWc];
__device__ float g_rstd[BB * GRP * HWc];
__device__ __half g_nh[(size_t)MM * CC];
__device__ __half g_wqh[C3 * CC];
__device__ __half g_wph[CC * CC];
__device__ __half g_qkv[(size_t)MM * C3];
__device__ __half g_ah[(size_t)MM * CC];
__device__ __half g_pout[(size_t)MM * CC];

// ---------------- helpers ----------------
__device__ __forceinline__ uint32_t smem_u32(const void* p) {
    uint32_t a;
    asm("{ .reg .u64 t; cvta.to.shared.u64 t, %1; cvt.u32.u64 %0, t; }" : "=r"(a) : "l"(p));
    return a;
}
__device__ __forceinline__ void cpasync16(uint32_t dst, const void* src) {
    asm volatile("cp.async.cg.shared.global [%0], [%1], 16;" :: "r"(dst), "l"(src));
}
__device__ __forceinline__ void ldsm4(uint32_t* r, uint32_t a) {
    asm volatile("ldmatrix.sync.aligned.m8n8.x4.shared.b16 {%0,%1,%2,%3}, [%4];"
                 : "=r"(r[0]), "=r"(r[1]), "=r"(r[2]), "=r"(r[3]) : "r"(a));
}
__device__ __forceinline__ void ldsm4t(uint32_t* r, uint32_t a) {
    asm volatile("ldmatrix.sync.aligned.m8n8.x4.trans.shared.b16 {%0,%1,%2,%3}, [%4];"
                 : "=r"(r[0]), "=r"(r[1]), "=r"(r[2]), "=r"(r[3]) : "r"(a));
}
__device__ __forceinline__ void mma16816(float* d, const uint32_t* a, uint32_t b0, uint32_t b1) {
    asm volatile(
        "mma.sync.aligned.m16n8k16.row.col.f32.f16.f16.f32 "
        "{%0,%1,%2,%3},{%4,%5,%6,%7},{%8,%9},{%0,%1,%2,%3};"
        : "+f"(d[0]), "+f"(d[1]), "+f"(d[2]), "+f"(d[3])
        : "r"(a[0]), "r"(a[1]), "r"(a[2]), "r"(a[3]), "r"(b0), "r"(b1));
}

// ---------------- 1) fused: group-norm stats + weight convert ----------------
__global__ __launch_bounds__(1024) void gn_conv(const float* __restrict__ x,
                                                const float* __restrict__ wq,
                                                const float* __restrict__ wp) {
    int bx = blockIdx.x;
    if (bx < 128) {
        int b  = bx >> 5;
        int g  = bx & 31;
        int hw = threadIdx.x;
        float sum = 0.f, sq = 0.f;
        const float* base = x + ((size_t)b * CC + (size_t)g * CPG) * TT * HWc + hw;
        #pragma unroll 4
        for (int ct = 0; ct < CPG * TT; ct++) {
            float v = base[(size_t)ct * HWc];
            sum += v; sq += v * v;
        }
        float m   = sum * (1.0f / 256.0f);
        float var = sq  * (1.0f / 256.0f) - m * m;
        g_mean[(size_t)bx * HWc + hw] = m;
        g_rstd[(size_t)bx * HWc + hw] = rsqrtf(var + EPSF);
    } else {
        int i4 = (bx - 128) * 1024 + threadIdx.x;
        constexpr int NQ4 = C3 * CC / 4;
        const float4* src;
        __half* h;
        int idx;
        if (i4 < NQ4) { src = (const float4*)wq; h = g_wqh; idx = i4; }
        else          { src = (const float4*)wp; h = g_wph; idx = i4 - NQ4; }
        float4 v = src[idx];
        __half hh[4] = {__float2half(v.x), __float2half(v.y),
                        __float2half(v.z), __float2half(v.w)};
        uint2 uh;
        uh.x = *(uint32_t*)&hh[0]; uh.y = *(uint32_t*)&hh[2];
        *(uint2*)(h + idx * 4) = uh;
    }
}

// ---------------- 2) normalize + transpose to fp16 [M,512] ----------------
__global__ __launch_bounds__(256) void norm_tr(const float* __restrict__ x,
                                               const float* __restrict__ gamma,
                                               const float* __restrict__ beta) {
    __shared__ float tile[32][33];
    int bx  = blockIdx.x;
    int hwt = bx & 31;
    int ct  = (bx >> 5) & 15;
    int t   = (bx >> 9) & 15;
    int b   = bx >> 13;
    int tid = threadIdx.x;
    {
        int hw_l = tid & 31;
        int c_l0 = tid >> 5;
        int hw   = hwt * 32 + hw_l;
        #pragma unroll
        for (int p = 0; p < 4; p++) {
            int c_l = c_l0 + p * 8;
            int c   = ct * 32 + c_l;
            int g   = c >> 4;
            float v = x[(((size_t)b * CC + c) * TT + t) * HWc + hw];
            size_t si = ((size_t)(b * GRP + g)) * HWc + hw;
            v = (v - g_mean[si]) * g_rstd[si] * gamma[c] + beta[c];
            tile[c_l][hw_l] = v;
        }
    }
    __syncthreads();
    {
        int c2    = (tid & 15) * 2;
        int hw_l0 = tid >> 4;
        #pragma unroll
        for (int p = 0; p < 2; p++) {
            int hw_l = hw_l0 + p * 16;
            int hw   = hwt * 32 + hw_l;
            size_t m = ((size_t)(b * HWc + hw)) * TT + t;
            float v0 = tile[c2][hw_l];
            float v1 = tile[c2 + 1][hw_l];
            size_t idx = m * CC + ct * 32 + c2;
            *(__half2*)(g_nh + idx) = __halves2half2(__float2half(v0), __float2half(v1));
        }
    }
}

// ---------------- HMMA GEMM (unchanged from R12) ----------------
constexpr int PITCH   = 80;
constexpr int TILE_B  = 128 * PITCH;
constexpr int STAGE_B = 2 * TILE_B;
constexpr int GEMM_SMEM = 4 * STAGE_B;

__global__ __launch_bounds__(256, 2) void hmma_gemm(const __half* __restrict__ A,
                                                    const __half* __restrict__ B,
                                                    const float* __restrict__ bias,
                                                    __half* __restrict__ Cout, int ldc) {
    extern __shared__ char smem[];
    uint32_t sb = smem_u32(smem);
    int tid = threadIdx.x;
    int n0 = blockIdx.x * 128;
    int m0 = blockIdx.y * 128;

    int r = tid >> 2;
    int c = tid & 3;
    const int4* pA = (const int4*)A + (size_t)(m0 + r) * 64 + c;
    const int4* pB = (const int4*)B + (size_t)(n0 + r) * 64 + c;
    uint32_t d0 = sb + r * PITCH + c * 16;
    constexpr int RSTEP = 64 * 64;
    constexpr int DSTEP = 64 * PITCH;

    auto issue = [&](int kk, int stage) {
        uint32_t dst = d0 + stage * STAGE_B;
        int ko = kk * 4;
        cpasync16(dst,                   pA + ko);
        cpasync16(dst + DSTEP,           pA + ko + RSTEP);
        cpasync16(dst + TILE_B,          pB + ko);
        cpasync16(dst + TILE_B + DSTEP,  pB + ko + RSTEP);
        asm volatile("cp.async.commit_group;");
    };

    float acc[4][4][4];
    #pragma unroll
    for (int a = 0; a < 4; a++)
        #pragma unroll
        for (int b = 0; b < 4; b++)
            #pragma unroll
            for (int cc = 0; cc < 4; cc++) acc[a][b][cc] = 0.f;

    int wid = tid >> 5, lane = tid & 31;
    int mw  = (wid >> 2) * 64;
    int nwv = (wid & 3) * 32;
    int lrow = lane & 15;
    int lk   = (lane >> 4) * 16;
    uint32_t adab = (mw + lrow) * PITCH + lk;
    uint32_t bdab = TILE_B + (nwv + lrow) * PITCH + lk;

    uint32_t amA[4][4], bmA[2][4];
    uint32_t amB[4][4], bmB[2][4];

    auto load_frags = [&](uint32_t am[4][4], uint32_t bm[2][4], uint32_t sa, int j) {
        #pragma unroll
        for (int mt = 0; mt < 4; mt++)
            ldsm4(am[mt], sa + adab + mt * (16 * PITCH) + j * 32);
        #pragma unroll
        for (int bt = 0; bt < 2; bt++)
            ldsm4(bm[bt], sa + bdab + bt * (16 * PITCH) + j * 32);
    };
    auto mma_all = [&](uint32_t am[4][4], uint32_t bm[2][4]) {
        #pragma unroll
        for (int mt = 0; mt < 4; mt++)
            #pragma unroll
            for (int nt = 0; nt < 4; nt++) {
                int bt = nt >> 1, s = nt & 1;
                mma16816(acc[mt][nt], am[mt], bm[bt][s], bm[bt][2 + s]);
            }
    };

    issue(0, 0);
    issue(1, 1);
    issue(2, 2);
    asm volatile("cp.async.wait_group 2;");
    __syncthreads();
    load_frags(amA, bmA, sb, 0);

    #pragma unroll 1
    for (int ks = 0; ks < 16; ks++) {
        if (ks < 14) asm volatile("cp.async.wait_group 1;");
        else         asm volatile("cp.async.wait_group 0;");
        __syncthreads();
        if (ks + 3 < 16) issue(ks + 3, (ks + 3) & 3);

        uint32_t sa  = sb + (ks & 3) * STAGE_B;
        uint32_t san = sb + ((ks + 1) & 3) * STAGE_B;

        load_frags(amB, bmB, sa, 1);
        mma_all(amA, bmA);
        if (ks < 15) load_frags(amA, bmA, san, 0);
        mma_all(amB, bmB);
    }

    int row_in = lane >> 2;
    int colq   = (lane & 3) * 2;
    #pragma unroll
    for (int mt = 0; mt < 4; mt++) {
        int gr = m0 + mw + mt * 16 + row_in;
        #pragma unroll
        for (int nt = 0; nt < 4; nt++) {
            int gc = n0 + nwv + nt * 8 + colq;
            float b0 = bias[gc], b1 = bias[gc + 1];
            *(__half2*)(Cout + (size_t)gr * ldc + gc) =
                __halves2half2(__float2half(acc[mt][nt][0] + b0),
                               __float2half(acc[mt][nt][1] + b1));
            *(__half2*)(Cout + (size_t)(gr + 8) * ldc + gc) =
                __halves2half2(__float2half(acc[mt][nt][2] + b0),
                               __float2half(acc[mt][nt][3] + b1));
        }
    }
}

// ---------------- 4) attention via HMMA: one warp = one head ----------------
constexpr int QPH  = 520;   // halves pitch q/k/v rows
constexpr int RPH  = 72;    // halves pitch rk/rv rows (32 rows, row31 zero)
constexpr int WSP  = 17;    // floats pitch Sc
constexpr int WRP  = 33;    // floats pitch R
constexpr int WP   = 24;    // halves pitch W
constexpr int W2P  = 40;    // halves pitch W'
constexpr int OFFB_Q  = 0;
constexpr int OFFB_K  = OFFB_Q  + 16 * QPH * 2;   // 16640
constexpr int OFFB_V  = OFFB_K  + 16 * QPH * 2;   // 33280
constexpr int OFFB_RK = OFFB_V  + 16 * QPH * 2;   // 49920
constexpr int OFFB_RV = OFFB_RK + 32 * RPH * 2;   // 54528
constexpr int OFFB_WS = OFFB_RV + 32 * RPH * 2;   // 59136
constexpr int OFFB_WR = OFFB_WS + 8 * 16 * WSP * 4;  // 67840
constexpr int OFFB_W  = OFFB_WR + 8 * 16 * WRP * 4;  // 84736
constexpr int OFFB_W2 = OFFB_W  + 8 * 16 * WP * 2;   // 90880
constexpr int ATTN_SMEM = OFFB_W2 + 8 * 16 * W2P * 2; // 101120

__global__ __launch_bounds__(256, 2) void attn(const float* __restrict__ rp_k,
                                               const float* __restrict__ rp_v) {
    extern __shared__ char smc[];
    uint32_t sb = smem_u32(smc);
    __half* rkh = (__half*)(smc + OFFB_RK);
    __half* rvh = (__half*)(smc + OFFB_RV);
    float*  wsf = (float*)(smc + OFFB_WS);
    float*  wrf = (float*)(smc + OFFB_WR);
    __half* wh  = (__half*)(smc + OFFB_W);
    __half* w2h = (__half*)(smc + OFFB_W2);

    int n   = blockIdx.x;
    int tid = threadIdx.x;
    int wid = tid >> 5, lane = tid & 31;

    // ---- load: bit-copy fp16 qkv ----
    const uint4* gq = reinterpret_cast<const uint4*>(g_qkv);
    #pragma unroll
    for (int it = 0; it < 12; it++) {
        int idx = it * 256 + tid;
        int t   = idx / 192;
        int rem = idx - t * 192;
        int which = rem >> 6;
        int c8    = rem & 63;
        uint4 raw = gq[(size_t)(n * TT + t) * 192 + rem];
        *(uint4*)(smc + OFFB_Q + which * (16 * QPH * 2) + (t * QPH + c8 * 8) * 2) = raw;
    }
    // rp rows 0..30 (dist 49..79), fp16; row 31 zero
    const float4* grk = reinterpret_cast<const float4*>(rp_k);
    const float4* grv = reinterpret_cast<const float4*>(rp_v);
    for (int idx = tid; idx < 992; idx += 256) {
        int hsel = idx >= 496;
        int r = idx - hsel * 496;
        int row = r >> 4, c4 = r & 15;
        float4 val = (hsel ? grv : grk)[(49 + row) * 16 + c4];
        __half h0 = __float2half(val.x), h1 = __float2half(val.y);
        __half h2 = __float2half(val.z), h3 = __float2half(val.w);
        uint2 u;
        u.x = ((uint32_t)*(uint16_t*)&h1 << 16) | *(uint16_t*)&h0;
        u.y = ((uint32_t)*(uint16_t*)&h3 << 16) | *(uint16_t*)&h2;
        *(uint2*)((hsel ? rvh : rkh) + row * RPH + c4 * 4) = u;
    }
    if (tid < 18) {
        int a = tid / 9, q4 = tid % 9;
        *(uint4*)((a ? rvh : rkh) + 31 * RPH + q4 * 8) = make_uint4(0, 0, 0, 0);
    }
    __syncthreads();

    // ---- score phase: Sc = Q*K^T (2 D-chunks), R = Q*RK^T (4 D-chunks) ----
    {
        int h = wid;
        int lrow = lane & 15;
        int lk8  = (lane >> 4) * 8;
        float accS[2][4], accR[4][4];
        #pragma unroll
        for (int i = 0; i < 2; i++)
            #pragma unroll
            for (int j = 0; j < 4; j++) accS[i][j] = 0.f;
        #pragma unroll
        for (int i = 0; i < 4; i++)
            #pragma unroll
            for (int j = 0; j < 4; j++) accR[i][j] = 0.f;

        #pragma unroll
        for (int kc = 0; kc < 4; kc++) {
            int coff = h * 64 + kc * 16 + lk8;
            uint32_t aq[4], bk[4], br0[4], br1[4];
            ldsm4(aq, sb + OFFB_Q + (lrow * QPH + coff) * 2);
            ldsm4(bk, sb + OFFB_K + (lrow * QPH + coff) * 2);
            ldsm4(br0, sb + OFFB_RK + (lrow * RPH + kc * 16 + lk8) * 2);
            ldsm4(br1, sb + OFFB_RK + ((lrow + 16) * RPH + kc * 16 + lk8) * 2);
            mma16816(accS[0], aq, bk[0], bk[2]);
            mma16816(accS[1], aq, bk[1], bk[3]);
            mma16816(accR[0], aq, br0[0], br0[2]);
            mma16816(accR[1], aq, br0[1], br0[3]);
            mma16816(accR[2], aq, br1[0], br1[2]);
            mma16816(accR[3], aq, br1[1], br1[3]);
        }
        // store D frags: row = lane>>2 (+8), col = (lane&3)*2 (+1)
        int dr = lane >> 2;
        int dc = (lane & 3) * 2;
        float* wsb = wsf + h * 16 * WSP;
        float* wrb = wrf + h * 16 * WRP;
        #pragma unroll
        for (int s = 0; s < 2; s++) {
            int col = s * 8 + dc;
            wsb[dr * WSP + col]           = accS[s][0];
            wsb[dr * WSP + col + 1]       = accS[s][1];
            wsb[(dr + 8) * WSP + col]     = accS[s][2];
            wsb[(dr + 8) * WSP + col + 1] = accS[s][3];
        }
        #pragma unroll
        for (int s = 0; s < 4; s++) {
            int col = s * 8 + dc;
            wrb[dr * WRP + col]           = accR[s][0];
            wrb[dr * WRP + col + 1]       = accR[s][1];
            wrb[(dr + 8) * WRP + col]     = accR[s][2];
            wrb[(dr + 8) * WRP + col + 1] = accR[s][3];
        }
    }
    __syncthreads();

    // ---- softmax: S[i][j] = 0.125*Sc[i][j] + 0.35355*R[j][i-j+15]; write W, W' fp16 ----
    if (tid < 128) {
        int h = tid >> 4, i = tid & 15;
        const float* wsb = wsf + h * 16 * WSP + i * WSP;
        const float* wrb = wrf + h * 16 * WRP;
        float s[16];
        float mx = -1e30f;
        #pragma unroll
        for (int j = 0; j < 16; j++) {
            s[j] = 0.125f * wsb[j] + 0.35355339059327373f * wrb[j * WRP + (i - j + 15)];
            mx = fmaxf(mx, s[j]);
        }
        float sum = 0.f;
        #pragma unroll
        for (int j = 0; j < 16; j++) { s[j] = __expf(s[j] - mx); sum += s[j]; }
        float inv = 1.f / sum;
        // zero W' row (cols 0..31)
        __half* w2b = w2h + (h * 16 + i) * W2P;
        #pragma unroll
        for (int q4 = 0; q4 < 4; q4++) *(uint4*)(w2b + q4 * 8) = make_uint4(0, 0, 0, 0);
        __half* wb = wh + (h * 16 + i) * WP;
        #pragma unroll
        for (int j = 0; j < 16; j++) {
            float w = s[j] * inv;
            __half hw_ = __float2half(w);
            wb[j] = hw_;
            w2b[j - i + 15] = hw_;
        }
    }
    __syncthreads();

    // ---- output phase: O = W*V + W'*RV ----
    {
        int h = wid;
        int lrow = lane & 15;
        int lk8  = (lane >> 4) * 8;
        float accO[8][4];
        #pragma unroll
        for (int i = 0; i < 8; i++)
            #pragma unroll
            for (int j = 0; j < 4; j++) accO[i][j] = 0.f;

        uint32_t aw[4], aw2a[4], aw2b[4];
        ldsm4(aw,   sb + OFFB_W  + (h * 16 * WP  + lrow * WP  + lk8) * 2);
        ldsm4(aw2a, sb + OFFB_W2 + (h * 16 * W2P + lrow * W2P + lk8) * 2);
        ldsm4(aw2b, sb + OFFB_W2 + (h * 16 * W2P + lrow * W2P + 16 + lk8) * 2);

        #pragma unroll
        for (int nc = 0; nc < 4; nc++) {
            int coff = h * 64 + nc * 16 + lk8;
            uint32_t bv[4], brv0[4], brv1[4];
            ldsm4t(bv,   sb + OFFB_V  + (lrow * QPH + coff) * 2);
            ldsm4t(brv0, sb + OFFB_RV + (lrow * RPH + nc * 16 + lk8) * 2);
            ldsm4t(brv1, sb + OFFB_RV + ((lrow + 16) * RPH + nc * 16 + lk8) * 2);
            // trans pairing: (r0,r1) = n-lo, (r2,r3) = n-hi
            mma16816(accO[nc * 2 + 0], aw, bv[0], bv[1]);
            mma16816(accO[nc * 2 + 1], aw, bv[2], bv[3]);
            mma16816(accO[nc * 2 + 0], aw2a, brv0[0], brv0[1]);
            mma16816(accO[nc * 2 + 1], aw2a, brv0[2], brv0[3]);
            mma16816(accO[nc * 2 + 0], aw2b, brv1[0], brv1[1]);
            mma16816(accO[nc * 2 + 1], aw2b, brv1[2], brv1[3]);
        }

        // epilogue: D row = t, col = c
        int dr = lane >> 2;
        int dc = (lane & 3) * 2;
        #pragma unroll
        for (int nc8 = 0; nc8 < 8; nc8++) {
            int col = h * 64 + nc8 * 8 + dc;
            size_t i0 = ((size_t)(n * TT + dr)) * CC + col;
            size_t i1 = ((size_t)(n * TT + dr + 8)) * CC + col;
            *(__half2*)(g_ah + i0) =
                __halves2half2(__float2half(accO[nc8][0]), __float2half(accO[nc8][1]));
            *(__half2*)(g_ah + i1) =
                __halves2half2(__float2half(accO[nc8][2]), __float2half(accO[nc8][3]));
        }
    }
}

// ---------------- 6) transpose back + residual (fp16 pout) ----------------
__global__ __launch_bounds__(256) void resid_tr(const float* __restrict__ x,
                                                float* __restrict__ out) {
    __shared__ float tile[32][33];
    int bx  = blockIdx.x;
    int hwt = bx & 31;
    int ct  = (bx >> 5) & 15;
    int t   = (bx >> 9) & 15;
    int b   = bx >> 13;
    int tid = threadIdx.x;
    {
        int c2    = (tid & 15) * 2;
        int hw_l0 = tid >> 4;
        #pragma unroll
        for (int p = 0; p < 2; p++) {
            int hw_l = hw_l0 + p * 16;
            int hw   = hwt * 32 + hw_l;
            size_t m = ((size_t)(b * HWc + hw)) * TT + t;
            __half2 hv = *(const __half2*)(g_pout + m * CC + ct * 32 + c2);
            float2 f = __half22float2(hv);
            tile[hw_l][c2]     = f.x;
            tile[hw_l][c2 + 1] = f.y;
        }
    }
    __syncthreads();
    {
        int hw_l = tid & 31;
        int c_l0 = tid >> 5;
        int hw   = hwt * 32 + hw_l;
        #pragma unroll
        for (int p = 0; p < 4; p++) {
            int c_l = c_l0 + p * 8;
            int c   = ct * 32 + c_l;
            size_t idx = (((size_t)b * CC + c) * TT + t) * HWc + hw;
            out[idx] = x[idx] + tile[hw_l][c_l];
        }
    }
}

// ---------------- host launch ----------------
extern "C" void kernel_launch(void* const* d_in, const int* in_sizes, int n_in,
                              void* d_out, int out_size) {
    const float* x      = (const float*)d_in[0];
    const float* gamma  = (const float*)d_in[1];
    const float* beta   = (const float*)d_in[2];
    const float* w_qkv  = (const float*)d_in[3];
    const float* b_qkv  = (const float*)d_in[4];
    const float* rp_k   = (const float*)d_in[5];
    const float* rp_v   = (const float*)d_in[6];
    const float* w_proj = (const float*)d_in[7];
    const float* b_proj = (const float*)d_in[8];
    float* out = (float*)d_out;

    cudaFuncSetAttribute(hmma_gemm, cudaFuncAttributeMaxDynamicSharedMemorySize, GEMM_SMEM);
    cudaFuncSetAttribute(attn, cudaFuncAttributeMaxDynamicSharedMemorySize, ATTN_SMEM);

    __half *wqh, *wph, *nh, *ah, *qkv, *pout;
    cudaGetSymbolAddress((void**)&wqh, g_wqh);
    cudaGetSymbolAddress((void**)&wph, g_wph);
    cudaGetSymbolAddress((void**)&nh, g_nh);
    cudaGetSymbolAddress((void**)&ah, g_ah);
    cudaGetSymbolAddress((void**)&qkv, g_qkv);
    cudaGetSymbolAddress((void**)&pout, g_pout);

    // attn stays launch #4 (ncu target: verify the HMMA rewrite)
    gn_conv<<<384, 1024>>>(x, w_qkv, w_proj);
    norm_tr<<<BB * TT * (CC / 32) * (HWc / 32), 256>>>(x, gamma, beta);
    hmma_gemm<<<dim3(C3 / 128, MM / 128), 256, GEMM_SMEM>>>(nh, wqh, b_qkv, qkv, C3);
    attn<<<NN, 256, ATTN_SMEM>>>(rp_k, rp_v);
    hmma_gemm<<<dim3(CC / 128, MM / 128), 256, GEMM_SMEM>>>(ah, wph, b_proj, pout, CC);
    resid_tr<<<BB * TT * (CC / 32) * (HWc / 32), 256>>>(x, out);
}